// round 5
// baseline (speedup 1.0000x reference)
#include <cuda_runtime.h>

#define B_ 8
#define S_ 1024
#define D_ 512
#define H_ 8
#define HD_ 64
#define NROWS (B_ * S_)   // 8192

// ---------------- scratch (static device globals; no runtime allocation) ----
__device__ float g_q[B_ * H_ * S_ * HD_];     // 16 MB, pre-scaled by 1/8
__device__ float g_k[B_ * H_ * S_ * HD_];     // 16 MB
__device__ float g_v[B_ * H_ * S_ * HD_];     // 16 MB
__device__ float g_mem[B_ * S_ * S_];         // 32 MB, normalized mem-attn probs
__device__ float g_att[NROWS * D_];           // 16 MB (attn out, later FFN out)
__device__ float g_o2[NROWS * D_];            // 16 MB (Wo out)

// ---------------------------------------------------------------------------
// GEMM: out[n, m] = sum_k X[n,k] * W[m,k] + bias[m]   (i.e. X @ W^T + b)
// 128x128 tile, BK=8, 256 threads, 8x8 micro-tile per thread.
// MODE 0: plain row-major out (NROWS x 512)
// MODE 1: qkv layout out[((b*H+h)*S+s)*HD+hd], scaled
// MODE 2: out = resid(g_o2) + (X @ W^T + b)
// SRC: 0 = external arg, 1 = g_att, 2 = g_o2
// DST: 0 g_q, 1 g_k, 2 g_v, 3 g_att, 4 g_o2
// ---------------------------------------------------------------------------
template <int MODE, int SRC, int DST>
__global__ __launch_bounds__(256) void gemm_kernel(
    const float* __restrict__ Xext, const float* __restrict__ W,
    const float* __restrict__ bias, float scale)
{
    const float* X = (SRC == 0) ? Xext : (SRC == 1) ? g_att : g_o2;
    float* out = (DST == 0) ? g_q : (DST == 1) ? g_k : (DST == 2) ? g_v
               : (DST == 3) ? g_att : g_o2;

    __shared__ float As[8][132];
    __shared__ float Bs[8][132];
    const int tid = threadIdx.x;
    const int n0 = blockIdx.x * 128;
    const int m0 = blockIdx.y * 128;
    const int lr = tid >> 1;          // 0..127 staging row
    const int lk = (tid & 1) * 4;     // 0 or 4 staging k
    const int ty = tid >> 4;          // 0..15
    const int tx = tid & 15;          // 0..15

    const float* Xp = X + (size_t)(n0 + lr) * D_ + lk;
    const float* Wp = W + (size_t)(m0 + lr) * D_ + lk;

    float acc[8][8];
#pragma unroll
    for (int i = 0; i < 8; i++)
#pragma unroll
        for (int j = 0; j < 8; j++) acc[i][j] = 0.0f;

    for (int k0 = 0; k0 < D_; k0 += 8) {
        float4 xa = *(const float4*)(Xp + k0);
        float4 wb = *(const float4*)(Wp + k0);
        __syncthreads();
        As[lk + 0][lr] = xa.x; As[lk + 1][lr] = xa.y;
        As[lk + 2][lr] = xa.z; As[lk + 3][lr] = xa.w;
        Bs[lk + 0][lr] = wb.x; Bs[lk + 1][lr] = wb.y;
        Bs[lk + 2][lr] = wb.z; Bs[lk + 3][lr] = wb.w;
        __syncthreads();
#pragma unroll
        for (int kk = 0; kk < 8; kk++) {
            float4 a0 = *(const float4*)&As[kk][ty * 8];
            float4 a1 = *(const float4*)&As[kk][ty * 8 + 4];
            float4 b0 = *(const float4*)&Bs[kk][tx * 8];
            float4 b1 = *(const float4*)&Bs[kk][tx * 8 + 4];
            float a[8] = {a0.x, a0.y, a0.z, a0.w, a1.x, a1.y, a1.z, a1.w};
            float b[8] = {b0.x, b0.y, b0.z, b0.w, b1.x, b1.y, b1.z, b1.w};
#pragma unroll
            for (int i = 0; i < 8; i++)
#pragma unroll
                for (int j = 0; j < 8; j++)
                    acc[i][j] = fmaf(a[i], b[j], acc[i][j]);
        }
    }

#pragma unroll
    for (int i = 0; i < 8; i++) {
        const int n = n0 + ty * 8 + i;
#pragma unroll
        for (int jq = 0; jq < 2; jq++) {
            const int m = m0 + tx * 8 + jq * 4;
            float4 o;
            o.x = acc[i][jq * 4 + 0] + bias[m + 0];
            o.y = acc[i][jq * 4 + 1] + bias[m + 1];
            o.z = acc[i][jq * 4 + 2] + bias[m + 2];
            o.w = acc[i][jq * 4 + 3] + bias[m + 3];
            if (MODE == 1) {
                o.x *= scale; o.y *= scale; o.z *= scale; o.w *= scale;
                const int bb = n >> 10, s = n & 1023;
                const int h = m >> 6, hd = m & 63;
                const size_t off = ((size_t)((bb * H_ + h) * S_ + s)) * HD_ + hd;
                *(float4*)(out + off) = o;
            } else if (MODE == 2) {
                const size_t off = (size_t)n * D_ + m;
                float4 rv = *(const float4*)(g_o2 + off);
                o.x += rv.x; o.y += rv.y; o.z += rv.z; o.w += rv.w;
                *(float4*)(out + off) = o;
            } else {
                *(float4*)(out + (size_t)n * D_ + m) = o;
            }
        }
    }
}

// ---------------------------------------------------------------------------
// mem-attention: for each (b,q): softmax_k over [ log10(ren+1) + exp(-|ts|) ]
// with causal mask (k<=q); normalized probs -> g_mem (0 where masked).
// One block per (b,q), 256 threads, 4 keys each.
// ---------------------------------------------------------------------------
__global__ __launch_bounds__(256) void mem_kernel(
    const float* __restrict__ ren, const float* __restrict__ ts)
{
    __shared__ float red[8];
    const int bq = blockIdx.x;
    const int q = bq & (S_ - 1);
    const float* rp = ren + (size_t)bq * S_;
    const float* tp = ts + (size_t)bq * S_;
    float* op = g_mem + (size_t)bq * S_;
    const int tid = threadIdx.x;
    const int k0 = tid * 4;

    float v[4];
    if (k0 <= q) {
        float4 rr = *(const float4*)(rp + k0);
        float4 tt = *(const float4*)(tp + k0);
        float rv[4] = {rr.x, rr.y, rr.z, rr.w};
        float tv[4] = {tt.x, tt.y, tt.z, tt.w};
#pragma unroll
        for (int j = 0; j < 4; j++)
            v[j] = (k0 + j <= q)
                       ? (__log10f(rv[j] + 1.0f) + __expf(-fabsf(tv[j])))
                       : -1e30f;
    } else {
        v[0] = v[1] = v[2] = v[3] = -1e30f;
    }

    float mx = fmaxf(fmaxf(v[0], v[1]), fmaxf(v[2], v[3]));
#pragma unroll
    for (int m = 16; m >= 1; m >>= 1)
        mx = fmaxf(mx, __shfl_xor_sync(0xffffffffu, mx, m));
    if ((tid & 31) == 0) red[tid >> 5] = mx;
    __syncthreads();
    if (tid < 32) {
        float t = (tid < 8) ? red[tid] : -1e30f;
#pragma unroll
        for (int m = 4; m >= 1; m >>= 1)
            t = fmaxf(t, __shfl_xor_sync(0xffffffffu, t, m));
        if (tid == 0) red[0] = t;
    }
    __syncthreads();
    mx = red[0];
    __syncthreads();

    float e[4];
    float s = 0.0f;
#pragma unroll
    for (int j = 0; j < 4; j++) { e[j] = __expf(v[j] - mx); s += e[j]; }
#pragma unroll
    for (int m = 16; m >= 1; m >>= 1)
        s += __shfl_xor_sync(0xffffffffu, s, m);
    if ((tid & 31) == 0) red[tid >> 5] = s;
    __syncthreads();
    if (tid < 32) {
        float t = (tid < 8) ? red[tid] : 0.0f;
#pragma unroll
        for (int m = 4; m >= 1; m >>= 1)
            t += __shfl_xor_sync(0xffffffffu, t, m);
        if (tid == 0) red[0] = t;
    }
    __syncthreads();
    const float inv = 1.0f / red[0];

    float4 o;
    o.x = e[0] * inv; o.y = e[1] * inv; o.z = e[2] * inv; o.w = e[3] * inv;
    *(float4*)(op + k0) = o;
}

// ---------------------------------------------------------------------------
// Flash-style causal attention blended with pre-normalized mem-attention.
// Block = one (b,h) x one 64-row q-tile. 256 threads, 4x4 micro-tile.
// out = (1-l)*softmax(QK^T) @ V  +  l * MEM @ V
// ---------------------------------------------------------------------------
#define ATT_STRIDE 68
#define ATT_SMEM_FLOATS (5 * 64 * ATT_STRIDE)

__global__ __launch_bounds__(256) void attn_kernel(const float* __restrict__ l1p)
{
    extern __shared__ float sm[];
    float(*Qs)[ATT_STRIDE] = (float(*)[ATT_STRIDE])sm;
    float(*Ks)[ATT_STRIDE] = (float(*)[ATT_STRIDE])(sm + 64 * ATT_STRIDE);
    float(*Vs)[ATT_STRIDE] = (float(*)[ATT_STRIDE])(sm + 2 * 64 * ATT_STRIDE);
    float(*Ps)[ATT_STRIDE] = (float(*)[ATT_STRIDE])(sm + 3 * 64 * ATT_STRIDE);
    float(*Ms)[ATT_STRIDE] = (float(*)[ATT_STRIDE])(sm + 4 * 64 * ATT_STRIDE);

    const int bh = blockIdx.x;
    const int qt = blockIdx.y;
    const int b = bh >> 3;
    const int h = bh & 7;
    const float l1 = *l1p;
    const float* Qg = g_q + (size_t)bh * S_ * HD_;
    const float* Kg = g_k + (size_t)bh * S_ * HD_;
    const float* Vg = g_v + (size_t)bh * S_ * HD_;
    const float* Mg = g_mem + (size_t)b * S_ * S_;

    const int tid = threadIdx.x;
    const int ty = tid >> 4, tx = tid & 15;
    const int lrow = tid >> 2;          // 0..63 staging row
    const int lc = (tid & 3) * 4;       // staging col base

    // stage Q tile transposed: Qs[d][r]
#pragma unroll
    for (int p = 0; p < 4; p++) {
        const int c0 = lc + p * 16;
        float4 v = *(const float4*)(Qg + (size_t)(qt * 64 + lrow) * HD_ + c0);
        Qs[c0 + 0][lrow] = v.x; Qs[c0 + 1][lrow] = v.y;
        Qs[c0 + 2][lrow] = v.z; Qs[c0 + 3][lrow] = v.w;
    }

    float m_i[4], lsum[4], acc1[4][4], acc2[4][4];
#pragma unroll
    for (int i = 0; i < 4; i++) {
        m_i[i] = -1e30f; lsum[i] = 0.0f;
#pragma unroll
        for (int j = 0; j < 4; j++) { acc1[i][j] = 0.0f; acc2[i][j] = 0.0f; }
    }

    for (int kt = 0; kt <= qt; kt++) {
        __syncthreads();   // previous iter's smem reads done (also fences Q staging)
#pragma unroll
        for (int p = 0; p < 4; p++) {
            const int c0 = lc + p * 16;
            const size_t rb = (size_t)(kt * 64 + lrow) * HD_ + c0;
            float4 kv = *(const float4*)(Kg + rb);
            float4 vv = *(const float4*)(Vg + rb);
            float4 mv = *(const float4*)(Mg + (size_t)(qt * 64 + lrow) * S_ + kt * 64 + c0);
            Ks[c0 + 0][lrow] = kv.x; Ks[c0 + 1][lrow] = kv.y;
            Ks[c0 + 2][lrow] = kv.z; Ks[c0 + 3][lrow] = kv.w;
            *(float4*)&Vs[lrow][c0] = vv;
            Ms[c0 + 0][lrow] = mv.x; Ms[c0 + 1][lrow] = mv.y;
            Ms[c0 + 2][lrow] = mv.z; Ms[c0 + 3][lrow] = mv.w;
        }
        __syncthreads();

        // scores tile (Q already scaled by 1/8)
        float s[4][4];
#pragma unroll
        for (int i = 0; i < 4; i++)
#pragma unroll
            for (int j = 0; j < 4; j++) s[i][j] = 0.0f;
#pragma unroll 16
        for (int d = 0; d < 64; d++) {
            float4 a = *(const float4*)&Qs[d][ty * 4];
            float4 bb = *(const float4*)&Ks[d][tx * 4];
            float av[4] = {a.x, a.y, a.z, a.w};
            float bv[4] = {bb.x, bb.y, bb.z, bb.w};
#pragma unroll
            for (int i = 0; i < 4; i++)
#pragma unroll
                for (int j = 0; j < 4; j++)
                    s[i][j] = fmaf(av[i], bv[j], s[i][j]);
        }
        if (kt == qt) {
#pragma unroll
            for (int i = 0; i < 4; i++)
#pragma unroll
                for (int j = 0; j < 4; j++)
                    if (tx * 4 + j > ty * 4 + i) s[i][j] = -1e30f;
        }

        // online softmax update per row (reduce across the 16-lane tx group)
#pragma unroll
        for (int i = 0; i < 4; i++) {
            float mt = fmaxf(fmaxf(s[i][0], s[i][1]), fmaxf(s[i][2], s[i][3]));
#pragma unroll
            for (int m = 8; m >= 1; m >>= 1)
                mt = fmaxf(mt, __shfl_xor_sync(0xffffffffu, mt, m));
            const float mn = fmaxf(m_i[i], mt);
            const float psc = __expf(m_i[i] - mn);
            m_i[i] = mn;
            float r = 0.0f;
#pragma unroll
            for (int j = 0; j < 4; j++) { s[i][j] = __expf(s[i][j] - mn); r += s[i][j]; }
#pragma unroll
            for (int m = 8; m >= 1; m >>= 1)
                r += __shfl_xor_sync(0xffffffffu, r, m);
            lsum[i] = lsum[i] * psc + r;
#pragma unroll
            for (int j = 0; j < 4; j++) acc1[i][j] *= psc;
        }

        // stage P transposed: Ps[c][r]
#pragma unroll
        for (int i = 0; i < 4; i++)
#pragma unroll
            for (int j = 0; j < 4; j++)
                Ps[tx * 4 + j][ty * 4 + i] = s[i][j];
        __syncthreads();

        // acc1 += P @ V ;  acc2 += MEM @ V
#pragma unroll 8
        for (int c = 0; c < 64; c++) {
            float4 p4 = *(const float4*)&Ps[c][ty * 4];
            float4 m4 = *(const float4*)&Ms[c][ty * 4];
            float4 v4 = *(const float4*)&Vs[c][tx * 4];
            float pv[4] = {p4.x, p4.y, p4.z, p4.w};
            float mv[4] = {m4.x, m4.y, m4.z, m4.w};
            float vv[4] = {v4.x, v4.y, v4.z, v4.w};
#pragma unroll
            for (int i = 0; i < 4; i++)
#pragma unroll
                for (int j = 0; j < 4; j++) {
                    acc1[i][j] = fmaf(pv[i], vv[j], acc1[i][j]);
                    acc2[i][j] = fmaf(mv[i], vv[j], acc2[i][j]);
                }
        }
    }

    const float w1 = 1.0f - l1;
#pragma unroll
    for (int i = 0; i < 4; i++) {
        const int srow = qt * 64 + ty * 4 + i;
        const float inv = w1 / lsum[i];
        float4 o;
        o.x = acc1[i][0] * inv + l1 * acc2[i][0];
        o.y = acc1[i][1] * inv + l1 * acc2[i][1];
        o.z = acc1[i][2] * inv + l1 * acc2[i][2];
        o.w = acc1[i][3] * inv + l1 * acc2[i][3];
        *(float4*)(g_att + ((size_t)(b * S_ + srow)) * D_ + h * HD_ + tx * 4) = o;
    }
}

// ---------------------------------------------------------------------------
// LayerNorm over D=512, one block (128 threads) per row. Reads g_att.
// ---------------------------------------------------------------------------
__global__ __launch_bounds__(128) void ln_kernel(
    const float* __restrict__ g, const float* __restrict__ bb,
    float* __restrict__ out)
{
    __shared__ float r1[4], r2[4];
    const int row = blockIdx.x;
    const int tid = threadIdx.x;
    const float* xr = g_att + (size_t)row * D_;
    float4 v = *(const float4*)(xr + tid * 4);
    float s = v.x + v.y + v.z + v.w;
    float sq = v.x * v.x + v.y * v.y + v.z * v.z + v.w * v.w;
#pragma unroll
    for (int m = 16; m >= 1; m >>= 1) {
        s += __shfl_xor_sync(0xffffffffu, s, m);
        sq += __shfl_xor_sync(0xffffffffu, sq, m);
    }
    if ((tid & 31) == 0) { r1[tid >> 5] = s; r2[tid >> 5] = sq; }
    __syncthreads();
    s = r1[0] + r1[1] + r1[2] + r1[3];
    sq = r2[0] + r2[1] + r2[2] + r2[3];
    const float mu = s * (1.0f / 512.0f);
    const float var = sq * (1.0f / 512.0f) - mu * mu;
    const float rstd = rsqrtf(var + 1e-5f);
    float4 gg = *(const float4*)(g + tid * 4);
    float4 bv = *(const float4*)(bb + tid * 4);
    float4 o;
    o.x = (v.x - mu) * rstd * gg.x + bv.x;
    o.y = (v.y - mu) * rstd * gg.y + bv.y;
    o.z = (v.z - mu) * rstd * gg.z + bv.z;
    o.w = (v.w - mu) * rstd * gg.w + bv.w;
    *(float4*)(out + (size_t)row * D_ + tid * 4) = o;
}

// ---------------------------------------------------------------------------
extern "C" void kernel_launch(void* const* d_in, const int* in_sizes, int n_in,
                              void* d_out, int out_size)
{
    (void)in_sizes; (void)n_in; (void)out_size;
    // metadata order: 0 query(unused) 1 inputs 2 ren_mat 3 timestamp 4 mask(unused)
    // 5 Wq 6 bq 7 Wk 8 bk 9 Wv 10 bv 11 Wo 12 bo 13 W1 14 b1 15 ln_g 16 ln_b 17 l1
    const float* inputs = (const float*)d_in[1];
    const float* ren    = (const float*)d_in[2];
    const float* tsp    = (const float*)d_in[3];
    const float* Wq = (const float*)d_in[5];
    const float* bq = (const float*)d_in[6];
    const float* Wk = (const float*)d_in[7];
    const float* bk = (const float*)d_in[8];
    const float* Wv = (const float*)d_in[9];
    const float* bv = (const float*)d_in[10];
    const float* Wo = (const float*)d_in[11];
    const float* bo = (const float*)d_in[12];
    const float* W1 = (const float*)d_in[13];
    const float* b1 = (const float*)d_in[14];
    const float* lng = (const float*)d_in[15];
    const float* lnb = (const float*)d_in[16];
    const float* l1  = (const float*)d_in[17];
    float* out = (float*)d_out;

    const dim3 ggrid(NROWS / 128, D_ / 128);

    // QKV projections (Q pre-scaled by 1/sqrt(HD)=0.125)
    gemm_kernel<1, 0, 0><<<ggrid, 256>>>(inputs, Wq, bq, 0.125f);
    gemm_kernel<1, 0, 1><<<ggrid, 256>>>(inputs, Wk, bk, 1.0f);
    gemm_kernel<1, 0, 2><<<ggrid, 256>>>(inputs, Wv, bv, 1.0f);

    // mem-attention probabilities (head-independent)
    mem_kernel<<<NROWS, 256>>>(ren, tsp);

    // blended flash attention -> g_att
    const int att_smem = ATT_SMEM_FLOATS * (int)sizeof(float);  // 87040 B
    cudaFuncSetAttribute(attn_kernel, cudaFuncAttributeMaxDynamicSharedMemorySize, att_smem);
    attn_kernel<<<dim3(B_ * H_, S_ / 64), 256, att_smem>>>(l1);

    // Wo projection: g_att @ Wo^T + bo -> g_o2
    gemm_kernel<0, 1, 4><<<ggrid, 256>>>(nullptr, Wo, bo, 1.0f);
    // FFN + residual: g_o2 + g_o2 @ W1^T + b1 -> g_att
    gemm_kernel<2, 2, 3><<<ggrid, 256>>>(nullptr, W1, b1, 1.0f);
    // LayerNorm -> d_out
    ln_kernel<<<NROWS, 128>>>(lng, lnb, out);
}

// round 10
// speedup vs baseline: 1.5788x; 1.5788x over previous
#include <cuda_runtime.h>
#include <cstdint>

#define B_ 8
#define S_ 1024
#define D_ 512
#define H_ 8
#define HD_ 64
#define NROWS (B_ * S_)   // 8192

// ---------------- scratch (static device globals; no runtime allocation) ----
__device__ float g_q[B_ * H_ * S_ * HD_];     // 16 MB, pre-scaled by 1/8
__device__ float g_k[B_ * H_ * S_ * HD_];     // 16 MB
__device__ float g_v[B_ * H_ * S_ * HD_];     // 16 MB
__device__ float g_mem[B_ * S_ * S_];         // 32 MB, normalized mem-attn probs
__device__ float g_att[NROWS * D_];           // 16 MB (attn out, later FFN out)
__device__ float g_o2[NROWS * D_];            // 16 MB (Wo out)

// ========================== mma.sync helpers ===============================
__device__ __forceinline__ uint32_t f2tf32(float f) {
    uint32_t r;
    asm("cvt.rna.tf32.f32 %0, %1;" : "=r"(r) : "f"(f));
    return r;
}

__device__ __forceinline__ void mma_16n8k8(float* c, const uint32_t* a,
                                           const uint32_t* b) {
    asm volatile(
        "mma.sync.aligned.m16n8k8.row.col.f32.tf32.tf32.f32 "
        "{%0,%1,%2,%3}, {%4,%5,%6,%7}, {%8,%9}, {%0,%1,%2,%3};"
        : "+f"(c[0]), "+f"(c[1]), "+f"(c[2]), "+f"(c[3])
        : "r"(a[0]), "r"(a[1]), "r"(a[2]), "r"(a[3]), "r"(b[0]), "r"(b[1]));
}

// ---------------------------------------------------------------------------
// Tensor GEMM via mma.sync tf32: out[n,m] = sum_k X[n,k]*W[m,k] + bias[m]
// 128x128 tile/CTA, 8 warps each 64x32, BK=32 double-buffered.
// MODE 0: row-major out; MODE 1: qkv layout + scale; MODE 2: resid(g_o2)+out
// SRC: 0 ext, 1 g_att, 2 g_o2.  DST: 0 g_q, 1 g_k, 2 g_v, 3 g_att, 4 g_o2
// ---------------------------------------------------------------------------
#define TG_STRIDE 36
#define TG_BUF (128 * TG_STRIDE)          // uint32 elems per matrix buffer
#define TG_SMEM (4 * TG_BUF * 4)          // bytes: A0,B0,A1,B1 = 73728

template <int MODE, int SRC, int DST>
__global__ __launch_bounds__(256, 1)
void tgemm_kernel(const float* __restrict__ Xext, const float* __restrict__ W,
                  const float* __restrict__ bias, float scale)
{
    const float* X = (SRC == 0) ? Xext : (SRC == 1) ? g_att : g_o2;
    float* out = (DST == 0) ? g_q : (DST == 1) ? g_k : (DST == 2) ? g_v
               : (DST == 3) ? g_att : g_o2;

    extern __shared__ uint32_t smu[];
    const int tid = threadIdx.x;
    const int wid = tid >> 5;
    const int lane = tid & 31;
    const int grp = lane >> 2;            // 0..7
    const int tig = lane & 3;             // 0..3
    const int wy = wid & 1;               // row half (64)
    const int wx = wid >> 1;              // col quarter (32)
    const int n0 = blockIdx.x * 128;
    const int m0 = blockIdx.y * 128;

    const int fr = tid >> 3;              // 0..31 staging row in 32-row group
    const int fc = tid & 7;               // float4 col index (0..7)
    const float* Ap = X + (size_t)(n0 + fr) * D_ + fc * 4;
    const float* Wp = W + (size_t)(m0 + fr) * D_ + fc * 4;

    float acc[4][4][4];
#pragma unroll
    for (int i = 0; i < 4; i++)
#pragma unroll
        for (int j = 0; j < 4; j++)
#pragma unroll
            for (int q = 0; q < 4; q++) acc[i][j][q] = 0.0f;

    float4 ra[4], rb[4];

    auto gload = [&](int c) {
        const int kb = c * 32;
#pragma unroll
        for (int g = 0; g < 4; g++) {
            ra[g] = *(const float4*)(Ap + kb + (size_t)g * 32 * D_);
            rb[g] = *(const float4*)(Wp + kb + (size_t)g * 32 * D_);
        }
    };
    auto sts = [&](int c) {
        uint32_t* bufA = smu + (c & 1) * 2 * TG_BUF;
        uint32_t* bufB = bufA + TG_BUF;
#pragma unroll
        for (int g = 0; g < 4; g++) {
            const uint32_t off = (uint32_t)(g * 32 + fr) * TG_STRIDE + fc * 4;
            uint4 a4 = {f2tf32(ra[g].x), f2tf32(ra[g].y),
                        f2tf32(ra[g].z), f2tf32(ra[g].w)};
            uint4 b4 = {f2tf32(rb[g].x), f2tf32(rb[g].y),
                        f2tf32(rb[g].z), f2tf32(rb[g].w)};
            *(uint4*)(bufA + off) = a4;
            *(uint4*)(bufB + off) = b4;
        }
    };
    auto compute = [&](int c) {
        const uint32_t* A = smu + (c & 1) * 2 * TG_BUF;
        const uint32_t* Bm = A + TG_BUF;
#pragma unroll
        for (int ks = 0; ks < 4; ks++) {
            const int kk = ks * 8 + tig;
            uint32_t af[4][4], bf[4][2];
#pragma unroll
            for (int rt = 0; rt < 4; rt++) {
                const int r = wy * 64 + rt * 16 + grp;
                af[rt][0] = A[r * TG_STRIDE + kk];
                af[rt][1] = A[(r + 8) * TG_STRIDE + kk];
                af[rt][2] = A[r * TG_STRIDE + kk + 4];
                af[rt][3] = A[(r + 8) * TG_STRIDE + kk + 4];
            }
#pragma unroll
            for (int ct = 0; ct < 4; ct++) {
                const int j = wx * 32 + ct * 8 + grp;
                bf[ct][0] = Bm[j * TG_STRIDE + kk];
                bf[ct][1] = Bm[j * TG_STRIDE + kk + 4];
            }
#pragma unroll
            for (int rt = 0; rt < 4; rt++)
#pragma unroll
                for (int ct = 0; ct < 4; ct++)
                    mma_16n8k8(acc[rt][ct], af[rt], bf[ct]);
        }
    };

    gload(0);
    sts(0);
    __syncthreads();
    for (int c = 0; c < 16; c++) {
        if (c < 15) gload(c + 1);
        compute(c);
        if (c < 15) sts(c + 1);
        __syncthreads();
    }

    // ---- epilogue ----
#pragma unroll
    for (int rt = 0; rt < 4; rt++) {
        const int n_lo = n0 + wy * 64 + rt * 16 + grp;
        const int n_hi = n_lo + 8;
#pragma unroll
        for (int ct = 0; ct < 4; ct++) {
            const int m2 = m0 + wx * 32 + ct * 8 + 2 * tig;
            const float2 bv = *(const float2*)(bias + m2);
            float2 lo, hi;
            lo.x = acc[rt][ct][0] + bv.x;
            lo.y = acc[rt][ct][1] + bv.y;
            hi.x = acc[rt][ct][2] + bv.x;
            hi.y = acc[rt][ct][3] + bv.y;
            if (MODE == 1) {
                lo.x *= scale; lo.y *= scale; hi.x *= scale; hi.y *= scale;
                const int h = m2 >> 6, hd = m2 & 63;
                const int blo = n_lo >> 10, slo = n_lo & 1023;
                const int bhi = n_hi >> 10, shi = n_hi & 1023;
                *(float2*)(out + ((size_t)((blo * H_ + h) * S_ + slo)) * HD_ + hd) = lo;
                *(float2*)(out + ((size_t)((bhi * H_ + h) * S_ + shi)) * HD_ + hd) = hi;
            } else if (MODE == 2) {
                const size_t off_lo = (size_t)n_lo * D_ + m2;
                const size_t off_hi = (size_t)n_hi * D_ + m2;
                float2 rlo = *(const float2*)(g_o2 + off_lo);
                float2 rhi = *(const float2*)(g_o2 + off_hi);
                lo.x += rlo.x; lo.y += rlo.y;
                hi.x += rhi.x; hi.y += rhi.y;
                *(float2*)(out + off_lo) = lo;
                *(float2*)(out + off_hi) = hi;
            } else {
                *(float2*)(out + (size_t)n_lo * D_ + m2) = lo;
                *(float2*)(out + (size_t)n_hi * D_ + m2) = hi;
            }
        }
    }
}

// ---------------------------------------------------------------------------
// mem-attention: softmax_k over [ log10(ren+1) + exp(-|ts|) ], causal, per (b,q)
// ---------------------------------------------------------------------------
__global__ __launch_bounds__(256) void mem_kernel(
    const float* __restrict__ ren, const float* __restrict__ ts)
{
    __shared__ float red[8];
    const int bq = blockIdx.x;
    const int q = bq & (S_ - 1);
    const float* rp = ren + (size_t)bq * S_;
    const float* tp = ts + (size_t)bq * S_;
    float* op = g_mem + (size_t)bq * S_;
    const int tid = threadIdx.x;
    const int k0 = tid * 4;

    float v[4];
    if (k0 <= q) {
        float4 rr = *(const float4*)(rp + k0);
        float4 tt = *(const float4*)(tp + k0);
        float rv[4] = {rr.x, rr.y, rr.z, rr.w};
        float tv[4] = {tt.x, tt.y, tt.z, tt.w};
#pragma unroll
        for (int j = 0; j < 4; j++)
            v[j] = (k0 + j <= q)
                       ? (__log10f(rv[j] + 1.0f) + __expf(-fabsf(tv[j])))
                       : -1e30f;
    } else {
        v[0] = v[1] = v[2] = v[3] = -1e30f;
    }

    float mx = fmaxf(fmaxf(v[0], v[1]), fmaxf(v[2], v[3]));
#pragma unroll
    for (int m = 16; m >= 1; m >>= 1)
        mx = fmaxf(mx, __shfl_xor_sync(0xffffffffu, mx, m));
    if ((tid & 31) == 0) red[tid >> 5] = mx;
    __syncthreads();
    if (tid < 32) {
        float t = (tid < 8) ? red[tid] : -1e30f;
#pragma unroll
        for (int m = 4; m >= 1; m >>= 1)
            t = fmaxf(t, __shfl_xor_sync(0xffffffffu, t, m));
        if (tid == 0) red[0] = t;
    }
    __syncthreads();
    mx = red[0];
    __syncthreads();

    float e[4];
    float s = 0.0f;
#pragma unroll
    for (int j = 0; j < 4; j++) { e[j] = __expf(v[j] - mx); s += e[j]; }
#pragma unroll
    for (int m = 16; m >= 1; m >>= 1)
        s += __shfl_xor_sync(0xffffffffu, s, m);
    if ((tid & 31) == 0) red[tid >> 5] = s;
    __syncthreads();
    if (tid < 32) {
        float t = (tid < 8) ? red[tid] : 0.0f;
#pragma unroll
        for (int m = 4; m >= 1; m >>= 1)
            t += __shfl_xor_sync(0xffffffffu, t, m);
        if (tid == 0) red[0] = t;
    }
    __syncthreads();
    const float inv = 1.0f / red[0];

    float4 o;
    o.x = e[0] * inv; o.y = e[1] * inv; o.z = e[2] * inv; o.w = e[3] * inv;
    *(float4*)(op + k0) = o;
}

// ---------------------------------------------------------------------------
// Flash-style causal attention blended with pre-normalized mem-attention.
// ---------------------------------------------------------------------------
#define ATT_STRIDE 68
#define ATT_SMEM_FLOATS (5 * 64 * ATT_STRIDE)

__global__ __launch_bounds__(256) void attn_kernel(const float* __restrict__ l1p)
{
    extern __shared__ float sm[];
    float(*Qs)[ATT_STRIDE] = (float(*)[ATT_STRIDE])sm;
    float(*Ks)[ATT_STRIDE] = (float(*)[ATT_STRIDE])(sm + 64 * ATT_STRIDE);
    float(*Vs)[ATT_STRIDE] = (float(*)[ATT_STRIDE])(sm + 2 * 64 * ATT_STRIDE);
    float(*Ps)[ATT_STRIDE] = (float(*)[ATT_STRIDE])(sm + 3 * 64 * ATT_STRIDE);
    float(*Ms)[ATT_STRIDE] = (float(*)[ATT_STRIDE])(sm + 4 * 64 * ATT_STRIDE);

    const int bh = blockIdx.x;
    const int qt = blockIdx.y;
    const int b = bh >> 3;
    const int h = bh & 7;
    const float l1 = *l1p;
    const float* Qg = g_q + (size_t)bh * S_ * HD_;
    const float* Kg = g_k + (size_t)bh * S_ * HD_;
    const float* Vg = g_v + (size_t)bh * S_ * HD_;
    const float* Mg = g_mem + (size_t)b * S_ * S_;

    const int tid = threadIdx.x;
    const int ty = tid >> 4, tx = tid & 15;
    const int lrow = tid >> 2;
    const int lc = (tid & 3) * 4;

#pragma unroll
    for (int p = 0; p < 4; p++) {
        const int c0 = lc + p * 16;
        float4 v = *(const float4*)(Qg + (size_t)(qt * 64 + lrow) * HD_ + c0);
        Qs[c0 + 0][lrow] = v.x; Qs[c0 + 1][lrow] = v.y;
        Qs[c0 + 2][lrow] = v.z; Qs[c0 + 3][lrow] = v.w;
    }

    float m_i[4], lsum[4], acc1[4][4], acc2[4][4];
#pragma unroll
    for (int i = 0; i < 4; i++) {
        m_i[i] = -1e30f; lsum[i] = 0.0f;
#pragma unroll
        for (int j = 0; j < 4; j++) { acc1[i][j] = 0.0f; acc2[i][j] = 0.0f; }
    }

    for (int kt = 0; kt <= qt; kt++) {
        __syncthreads();
#pragma unroll
        for (int p = 0; p < 4; p++) {
            const int c0 = lc + p * 16;
            const size_t rb = (size_t)(kt * 64 + lrow) * HD_ + c0;
            float4 kv = *(const float4*)(Kg + rb);
            float4 vv = *(const float4*)(Vg + rb);
            float4 mv = *(const float4*)(Mg + (size_t)(qt * 64 + lrow) * S_ + kt * 64 + c0);
            Ks[c0 + 0][lrow] = kv.x; Ks[c0 + 1][lrow] = kv.y;
            Ks[c0 + 2][lrow] = kv.z; Ks[c0 + 3][lrow] = kv.w;
            *(float4*)&Vs[lrow][c0] = vv;
            Ms[c0 + 0][lrow] = mv.x; Ms[c0 + 1][lrow] = mv.y;
            Ms[c0 + 2][lrow] = mv.z; Ms[c0 + 3][lrow] = mv.w;
        }
        __syncthreads();

        float s[4][4];
#pragma unroll
        for (int i = 0; i < 4; i++)
#pragma unroll
            for (int j = 0; j < 4; j++) s[i][j] = 0.0f;
#pragma unroll 16
        for (int d = 0; d < 64; d++) {
            float4 a = *(const float4*)&Qs[d][ty * 4];
            float4 bb = *(const float4*)&Ks[d][tx * 4];
            float av[4] = {a.x, a.y, a.z, a.w};
            float bv[4] = {bb.x, bb.y, bb.z, bb.w};
#pragma unroll
            for (int i = 0; i < 4; i++)
#pragma unroll
                for (int j = 0; j < 4; j++)
                    s[i][j] = fmaf(av[i], bv[j], s[i][j]);
        }
        if (kt == qt) {
#pragma unroll
            for (int i = 0; i < 4; i++)
#pragma unroll
                for (int j = 0; j < 4; j++)
                    if (tx * 4 + j > ty * 4 + i) s[i][j] = -1e30f;
        }

#pragma unroll
        for (int i = 0; i < 4; i++) {
            float mt = fmaxf(fmaxf(s[i][0], s[i][1]), fmaxf(s[i][2], s[i][3]));
#pragma unroll
            for (int m = 8; m >= 1; m >>= 1)
                mt = fmaxf(mt, __shfl_xor_sync(0xffffffffu, mt, m));
            const float mn = fmaxf(m_i[i], mt);
            const float psc = __expf(m_i[i] - mn);
            m_i[i] = mn;
            float r = 0.0f;
#pragma unroll
            for (int j = 0; j < 4; j++) { s[i][j] = __expf(s[i][j] - mn); r += s[i][j]; }
#pragma unroll
            for (int m = 8; m >= 1; m >>= 1)
                r += __shfl_xor_sync(0xffffffffu, r, m);
            lsum[i] = lsum[i] * psc + r;
#pragma unroll
            for (int j = 0; j < 4; j++) acc1[i][j] *= psc;
        }

#pragma unroll
        for (int i = 0; i < 4; i++)
#pragma unroll
            for (int j = 0; j < 4; j++)
                Ps[tx * 4 + j][ty * 4 + i] = s[i][j];
        __syncthreads();

#pragma unroll 8
        for (int c = 0; c < 64; c++) {
            float4 p4 = *(const float4*)&Ps[c][ty * 4];
            float4 m4 = *(const float4*)&Ms[c][ty * 4];
            float4 v4 = *(const float4*)&Vs[c][tx * 4];
            float pv[4] = {p4.x, p4.y, p4.z, p4.w};
            float mv[4] = {m4.x, m4.y, m4.z, m4.w};
            float vv[4] = {v4.x, v4.y, v4.z, v4.w};
#pragma unroll
            for (int i = 0; i < 4; i++)
#pragma unroll
                for (int j = 0; j < 4; j++) {
                    acc1[i][j] = fmaf(pv[i], vv[j], acc1[i][j]);
                    acc2[i][j] = fmaf(mv[i], vv[j], acc2[i][j]);
                }
        }
    }

    const float w1 = 1.0f - l1;
#pragma unroll
    for (int i = 0; i < 4; i++) {
        const int srow = qt * 64 + ty * 4 + i;
        const float inv = w1 / lsum[i];
        float4 o;
        o.x = acc1[i][0] * inv + l1 * acc2[i][0];
        o.y = acc1[i][1] * inv + l1 * acc2[i][1];
        o.z = acc1[i][2] * inv + l1 * acc2[i][2];
        o.w = acc1[i][3] * inv + l1 * acc2[i][3];
        *(float4*)(g_att + ((size_t)(b * S_ + srow)) * D_ + h * HD_ + tx * 4) = o;
    }
}

// ---------------------------------------------------------------------------
// LayerNorm over D=512, one block (128 threads) per row. Reads g_att.
// ---------------------------------------------------------------------------
__global__ __launch_bounds__(128) void ln_kernel(
    const float* __restrict__ g, const float* __restrict__ bb,
    float* __restrict__ out)
{
    __shared__ float r1[4], r2[4];
    const int row = blockIdx.x;
    const int tid = threadIdx.x;
    const float* xr = g_att + (size_t)row * D_;
    float4 v = *(const float4*)(xr + tid * 4);
    float s = v.x + v.y + v.z + v.w;
    float sq = v.x * v.x + v.y * v.y + v.z * v.z + v.w * v.w;
#pragma unroll
    for (int m = 16; m >= 1; m >>= 1) {
        s += __shfl_xor_sync(0xffffffffu, s, m);
        sq += __shfl_xor_sync(0xffffffffu, sq, m);
    }
    if ((tid & 31) == 0) { r1[tid >> 5] = s; r2[tid >> 5] = sq; }
    __syncthreads();
    s = r1[0] + r1[1] + r1[2] + r1[3];
    sq = r2[0] + r2[1] + r2[2] + r2[3];
    const float mu = s * (1.0f / 512.0f);
    const float var = sq * (1.0f / 512.0f) - mu * mu;
    const float rstd = rsqrtf(var + 1e-5f);
    float4 gg = *(const float4*)(g + tid * 4);
    float4 bv = *(const float4*)(bb + tid * 4);
    float4 o;
    o.x = (v.x - mu) * rstd * gg.x + bv.x;
    o.y = (v.y - mu) * rstd * gg.y + bv.y;
    o.z = (v.z - mu) * rstd * gg.z + bv.z;
    o.w = (v.w - mu) * rstd * gg.w + bv.w;
    *(float4*)(out + (size_t)row * D_ + tid * 4) = o;
}

// ---------------------------------------------------------------------------
extern "C" void kernel_launch(void* const* d_in, const int* in_sizes, int n_in,
                              void* d_out, int out_size)
{
    (void)in_sizes; (void)n_in; (void)out_size;
    const float* inputs = (const float*)d_in[1];
    const float* ren    = (const float*)d_in[2];
    const float* tsp    = (const float*)d_in[3];
    const float* Wq = (const float*)d_in[5];
    const float* bq = (const float*)d_in[6];
    const float* Wk = (const float*)d_in[7];
    const float* bk = (const float*)d_in[8];
    const float* Wv = (const float*)d_in[9];
    const float* bv = (const float*)d_in[10];
    const float* Wo = (const float*)d_in[11];
    const float* bo = (const float*)d_in[12];
    const float* W1 = (const float*)d_in[13];
    const float* b1 = (const float*)d_in[14];
    const float* lng = (const float*)d_in[15];
    const float* lnb = (const float*)d_in[16];
    const float* l1  = (const float*)d_in[17];
    float* out = (float*)d_out;

    cudaFuncSetAttribute(tgemm_kernel<1, 0, 0>, cudaFuncAttributeMaxDynamicSharedMemorySize, TG_SMEM);
    cudaFuncSetAttribute(tgemm_kernel<1, 0, 1>, cudaFuncAttributeMaxDynamicSharedMemorySize, TG_SMEM);
    cudaFuncSetAttribute(tgemm_kernel<1, 0, 2>, cudaFuncAttributeMaxDynamicSharedMemorySize, TG_SMEM);
    cudaFuncSetAttribute(tgemm_kernel<0, 1, 4>, cudaFuncAttributeMaxDynamicSharedMemorySize, TG_SMEM);
    cudaFuncSetAttribute(tgemm_kernel<2, 2, 3>, cudaFuncAttributeMaxDynamicSharedMemorySize, TG_SMEM);

    const dim3 ggrid(NROWS / 128, D_ / 128);

    // QKV projections (Q pre-scaled by 1/sqrt(HD)=0.125) — mma.sync tf32
    tgemm_kernel<1, 0, 0><<<ggrid, 256, TG_SMEM>>>(inputs, Wq, bq, 0.125f);
    tgemm_kernel<1, 0, 1><<<ggrid, 256, TG_SMEM>>>(inputs, Wk, bk, 1.0f);
    tgemm_kernel<1, 0, 2><<<ggrid, 256, TG_SMEM>>>(inputs, Wv, bv, 1.0f);

    // mem-attention probabilities (head-independent)
    mem_kernel<<<NROWS, 256>>>(ren, tsp);

    // blended flash attention -> g_att
    const int att_smem = ATT_SMEM_FLOATS * (int)sizeof(float);  // 87040 B
    cudaFuncSetAttribute(attn_kernel, cudaFuncAttributeMaxDynamicSharedMemorySize, att_smem);
    attn_kernel<<<dim3(B_ * H_, S_ / 64), 256, att_smem>>>(l1);

    // Wo projection: g_att @ Wo^T + bo -> g_o2
    tgemm_kernel<0, 1, 4><<<ggrid, 256, TG_SMEM>>>(nullptr, Wo, bo, 1.0f);
    // FFN + residual: g_o2 + g_o2 @ W1^T + b1 -> g_att
    tgemm_kernel<2, 2, 3><<<ggrid, 256, TG_SMEM>>>(nullptr, W1, b1, 1.0f);
    // LayerNorm -> d_out
    ln_kernel<<<NROWS, 128>>>(lng, lnb, out);
}

// round 12
// speedup vs baseline: 2.6477x; 1.6770x over previous
#include <cuda_runtime.h>
#include <cstdint>

#define B_ 8
#define S_ 1024
#define D_ 512
#define H_ 8
#define HD_ 64
#define NROWS (B_ * S_)   // 8192

// ---------------- scratch (static device globals; no runtime allocation) ----
// g_q/g_k/g_v/g_mem hold tf32-rounded fp32 bit patterns (produced rounded).
__device__ float g_q[B_ * H_ * S_ * HD_];     // 16 MB, pre-scaled by 1/8
__device__ float g_k[B_ * H_ * S_ * HD_];     // 16 MB
__device__ float g_v[B_ * H_ * S_ * HD_];     // 16 MB
__device__ float g_mem[B_ * S_ * S_];         // 32 MB, normalized mem-attn probs
__device__ float g_att[NROWS * D_];           // 16 MB (attn out, later FFN out)
__device__ float g_o2[NROWS * D_];            // 16 MB (Wo out)

// ========================== mma.sync helpers ===============================
__device__ __forceinline__ uint32_t f2tf32(float f) {
    uint32_t r;
    asm("cvt.rna.tf32.f32 %0, %1;" : "=r"(r) : "f"(f));
    return r;
}

__device__ __forceinline__ void mma_16n8k8(float* c, const uint32_t* a,
                                           const uint32_t* b) {
    asm volatile(
        "mma.sync.aligned.m16n8k8.row.col.f32.tf32.tf32.f32 "
        "{%0,%1,%2,%3}, {%4,%5,%6,%7}, {%8,%9}, {%0,%1,%2,%3};"
        : "+f"(c[0]), "+f"(c[1]), "+f"(c[2]), "+f"(c[3])
        : "r"(a[0]), "r"(a[1]), "r"(a[2]), "r"(a[3]), "r"(b[0]), "r"(b[1]));
}

// ---------------------------------------------------------------------------
// Tensor GEMM via mma.sync tf32: out[n,m] = sum_k X[n,k]*W[m,k] + bias[m]
// 128x128 tile/CTA, 8 warps each 64x32, BK=32 double-buffered.
// MODE 0: plain out; MODE 1: qkv layout + scale + tf32-round; MODE 2: resid
// SRC: 0 ext, 1 g_att, 2 g_o2.  DST: 0 g_q, 1 g_k, 2 g_v, 3 g_att, 4 g_o2
// ---------------------------------------------------------------------------
#define TG_STRIDE 36
#define TG_BUF (128 * TG_STRIDE)
#define TG_SMEM (4 * TG_BUF * 4)          // 73728 B

template <int MODE, int SRC, int DST>
__global__ __launch_bounds__(256, 1)
void tgemm_kernel(const float* __restrict__ Xext, const float* __restrict__ W,
                  const float* __restrict__ bias, float scale)
{
    const float* X = (SRC == 0) ? Xext : (SRC == 1) ? g_att : g_o2;
    float* out = (DST == 0) ? g_q : (DST == 1) ? g_k : (DST == 2) ? g_v
               : (DST == 3) ? g_att : g_o2;

    extern __shared__ uint32_t smu[];
    const int tid = threadIdx.x;
    const int wid = tid >> 5;
    const int lane = tid & 31;
    const int grp = lane >> 2;
    const int tig = lane & 3;
    const int wy = wid & 1;
    const int wx = wid >> 1;
    const int n0 = blockIdx.x * 128;
    const int m0 = blockIdx.y * 128;

    const int fr = tid >> 3;
    const int fc = tid & 7;
    const float* Ap = X + (size_t)(n0 + fr) * D_ + fc * 4;
    const float* Wp = W + (size_t)(m0 + fr) * D_ + fc * 4;

    float acc[4][4][4];
#pragma unroll
    for (int i = 0; i < 4; i++)
#pragma unroll
        for (int j = 0; j < 4; j++)
#pragma unroll
            for (int q = 0; q < 4; q++) acc[i][j][q] = 0.0f;

    float4 ra[4], rb[4];

    auto gload = [&](int c) {
        const int kb = c * 32;
#pragma unroll
        for (int g = 0; g < 4; g++) {
            ra[g] = *(const float4*)(Ap + kb + (size_t)g * 32 * D_);
            rb[g] = *(const float4*)(Wp + kb + (size_t)g * 32 * D_);
        }
    };
    auto sts = [&](int c) {
        uint32_t* bufA = smu + (c & 1) * 2 * TG_BUF;
        uint32_t* bufB = bufA + TG_BUF;
#pragma unroll
        for (int g = 0; g < 4; g++) {
            const uint32_t off = (uint32_t)(g * 32 + fr) * TG_STRIDE + fc * 4;
            uint4 a4 = {f2tf32(ra[g].x), f2tf32(ra[g].y),
                        f2tf32(ra[g].z), f2tf32(ra[g].w)};
            uint4 b4 = {f2tf32(rb[g].x), f2tf32(rb[g].y),
                        f2tf32(rb[g].z), f2tf32(rb[g].w)};
            *(uint4*)(bufA + off) = a4;
            *(uint4*)(bufB + off) = b4;
        }
    };
    auto compute = [&](int c) {
        const uint32_t* A = smu + (c & 1) * 2 * TG_BUF;
        const uint32_t* Bm = A + TG_BUF;
#pragma unroll
        for (int ks = 0; ks < 4; ks++) {
            const int kk = ks * 8 + tig;
            uint32_t af[4][4], bf[4][2];
#pragma unroll
            for (int rt = 0; rt < 4; rt++) {
                const int r = wy * 64 + rt * 16 + grp;
                af[rt][0] = A[r * TG_STRIDE + kk];
                af[rt][1] = A[(r + 8) * TG_STRIDE + kk];
                af[rt][2] = A[r * TG_STRIDE + kk + 4];
                af[rt][3] = A[(r + 8) * TG_STRIDE + kk + 4];
            }
#pragma unroll
            for (int ct = 0; ct < 4; ct++) {
                const int j = wx * 32 + ct * 8 + grp;
                bf[ct][0] = Bm[j * TG_STRIDE + kk];
                bf[ct][1] = Bm[j * TG_STRIDE + kk + 4];
            }
#pragma unroll
            for (int rt = 0; rt < 4; rt++)
#pragma unroll
                for (int ct = 0; ct < 4; ct++)
                    mma_16n8k8(acc[rt][ct], af[rt], bf[ct]);
        }
    };

    gload(0);
    sts(0);
    __syncthreads();
    for (int c = 0; c < 16; c++) {
        if (c < 15) gload(c + 1);
        compute(c);
        if (c < 15) sts(c + 1);
        __syncthreads();
    }

#pragma unroll
    for (int rt = 0; rt < 4; rt++) {
        const int n_lo = n0 + wy * 64 + rt * 16 + grp;
        const int n_hi = n_lo + 8;
#pragma unroll
        for (int ct = 0; ct < 4; ct++) {
            const int m2 = m0 + wx * 32 + ct * 8 + 2 * tig;
            const float2 bv = *(const float2*)(bias + m2);
            float2 lo, hi;
            lo.x = acc[rt][ct][0] + bv.x;
            lo.y = acc[rt][ct][1] + bv.y;
            hi.x = acc[rt][ct][2] + bv.x;
            hi.y = acc[rt][ct][3] + bv.y;
            if (MODE == 1) {
                lo.x = __uint_as_float(f2tf32(lo.x * scale));
                lo.y = __uint_as_float(f2tf32(lo.y * scale));
                hi.x = __uint_as_float(f2tf32(hi.x * scale));
                hi.y = __uint_as_float(f2tf32(hi.y * scale));
                const int h = m2 >> 6, hd = m2 & 63;
                const int blo = n_lo >> 10, slo = n_lo & 1023;
                const int bhi = n_hi >> 10, shi = n_hi & 1023;
                *(float2*)(out + ((size_t)((blo * H_ + h) * S_ + slo)) * HD_ + hd) = lo;
                *(float2*)(out + ((size_t)((bhi * H_ + h) * S_ + shi)) * HD_ + hd) = hi;
            } else if (MODE == 2) {
                const size_t off_lo = (size_t)n_lo * D_ + m2;
                const size_t off_hi = (size_t)n_hi * D_ + m2;
                float2 rlo = *(const float2*)(g_o2 + off_lo);
                float2 rhi = *(const float2*)(g_o2 + off_hi);
                lo.x += rlo.x; lo.y += rlo.y;
                hi.x += rhi.x; hi.y += rhi.y;
                *(float2*)(out + off_lo) = lo;
                *(float2*)(out + off_hi) = hi;
            } else {
                *(float2*)(out + (size_t)n_lo * D_ + m2) = lo;
                *(float2*)(out + (size_t)n_hi * D_ + m2) = hi;
            }
        }
    }
}

// ---------------------------------------------------------------------------
// mem-attention: softmax_k over [ log10(ren+1) + exp(-|ts|) ], causal, per (b,q)
// Output probs rounded to tf32 (consumed only by tensor-core MV GEMM).
// ---------------------------------------------------------------------------
__global__ __launch_bounds__(256) void mem_kernel(
    const float* __restrict__ ren, const float* __restrict__ ts)
{
    __shared__ float red[8];
    const int bq = blockIdx.x;
    const int q = bq & (S_ - 1);
    const float* rp = ren + (size_t)bq * S_;
    const float* tp = ts + (size_t)bq * S_;
    float* op = g_mem + (size_t)bq * S_;
    const int tid = threadIdx.x;
    const int k0 = tid * 4;

    float v[4];
    if (k0 <= q) {
        float4 rr = *(const float4*)(rp + k0);
        float4 tt = *(const float4*)(tp + k0);
        float rv[4] = {rr.x, rr.y, rr.z, rr.w};
        float tv[4] = {tt.x, tt.y, tt.z, tt.w};
#pragma unroll
        for (int j = 0; j < 4; j++)
            v[j] = (k0 + j <= q)
                       ? (__log10f(rv[j] + 1.0f) + __expf(-fabsf(tv[j])))
                       : -1e30f;
    } else {
        v[0] = v[1] = v[2] = v[3] = -1e30f;
    }

    float mx = fmaxf(fmaxf(v[0], v[1]), fmaxf(v[2], v[3]));
#pragma unroll
    for (int m = 16; m >= 1; m >>= 1)
        mx = fmaxf(mx, __shfl_xor_sync(0xffffffffu, mx, m));
    if ((tid & 31) == 0) red[tid >> 5] = mx;
    __syncthreads();
    if (tid < 32) {
        float t = (tid < 8) ? red[tid] : -1e30f;
#pragma unroll
        for (int m = 4; m >= 1; m >>= 1)
            t = fmaxf(t, __shfl_xor_sync(0xffffffffu, t, m));
        if (tid == 0) red[0] = t;
    }
    __syncthreads();
    mx = red[0];
    __syncthreads();

    float e[4];
    float s = 0.0f;
#pragma unroll
    for (int j = 0; j < 4; j++) { e[j] = __expf(v[j] - mx); s += e[j]; }
#pragma unroll
    for (int m = 16; m >= 1; m >>= 1)
        s += __shfl_xor_sync(0xffffffffu, s, m);
    if ((tid & 31) == 0) red[tid >> 5] = s;
    __syncthreads();
    if (tid < 32) {
        float t = (tid < 8) ? red[tid] : 0.0f;
#pragma unroll
        for (int m = 4; m >= 1; m >>= 1)
            t += __shfl_xor_sync(0xffffffffu, t, m);
        if (tid == 0) red[0] = t;
    }
    __syncthreads();
    const float inv = 1.0f / red[0];

    float4 o;
    o.x = __uint_as_float(f2tf32(e[0] * inv));
    o.y = __uint_as_float(f2tf32(e[1] * inv));
    o.z = __uint_as_float(f2tf32(e[2] * inv));
    o.w = __uint_as_float(f2tf32(e[3] * inv));
    *(float4*)(op + k0) = o;
}

// ---------------------------------------------------------------------------
// Flash attention + mem-attention blend, mma.sync tf32.
// 128 threads (4 warps); warp w owns q-rows [w*16, w*16+16).
// S = Q K^T (tensor), online softmax on fragments, PV and MV share B-frags.
// ---------------------------------------------------------------------------
#define AT_STRIDE 68
#define AT_SMEM (4 * 64 * AT_STRIDE * 4)   // Ks,Vs,Ms,Ps = 69632 B

__global__ __launch_bounds__(128) void attn_kernel(const float* __restrict__ l1p)
{
    extern __shared__ uint32_t su[];
    uint32_t* Ks = su;
    uint32_t* Vs = su + 64 * AT_STRIDE;
    uint32_t* Ms = su + 2 * 64 * AT_STRIDE;
    uint32_t* Ps = su + 3 * 64 * AT_STRIDE;

    const int bh = blockIdx.x;
    const int qt = blockIdx.y;
    const int b = bh >> 3;
    const int h = bh & 7;
    const int tid = threadIdx.x;
    const int wid = tid >> 5;
    const int lane = tid & 31;
    const int grp = lane >> 2;
    const int tig = lane & 3;
    const int r0 = wid * 16 + grp;     // q row within tile
    const int r1 = r0 + 8;

    const uint32_t* Qg = (const uint32_t*)g_q + (size_t)bh * S_ * HD_
                         + (size_t)qt * 64 * HD_;
    const uint32_t* Kg = (const uint32_t*)g_k + (size_t)bh * S_ * HD_;
    const uint32_t* Vg = (const uint32_t*)g_v + (size_t)bh * S_ * HD_;
    const uint32_t* Mg = (const uint32_t*)g_mem + (size_t)b * S_ * S_;
    const float l1v = *l1p;

    // Q fragments, loop-invariant (values pre-rounded to tf32)
    uint32_t aQ[8][4];
#pragma unroll
    for (int ks = 0; ks < 8; ks++) {
        aQ[ks][0] = Qg[r0 * HD_ + 8 * ks + tig];
        aQ[ks][1] = Qg[r1 * HD_ + 8 * ks + tig];
        aQ[ks][2] = Qg[r0 * HD_ + 8 * ks + tig + 4];
        aQ[ks][3] = Qg[r1 * HD_ + 8 * ks + tig + 4];
    }

    float mi0 = -1e30f, mi1 = -1e30f, ls0 = 0.0f, ls1 = 0.0f;
    float accPV[8][4], accMV[8][4];
#pragma unroll
    for (int nt = 0; nt < 8; nt++)
#pragma unroll
        for (int q = 0; q < 4; q++) { accPV[nt][q] = 0.0f; accMV[nt][q] = 0.0f; }

    for (int kt = 0; kt <= qt; kt++) {
        __syncthreads();
        // stage K,V (rows kt*64..) and M (rows qt*64.., cols kt*64..), plain copy
#pragma unroll
        for (int p = 0; p < 8; p++) {
            const int idx = tid + p * 128;
            const int row = idx >> 4;
            const int c4 = (idx & 15) * 4;
            uint4 kv = *(const uint4*)(Kg + (size_t)(kt * 64 + row) * HD_ + c4);
            uint4 vv = *(const uint4*)(Vg + (size_t)(kt * 64 + row) * HD_ + c4);
            uint4 mv = *(const uint4*)(Mg + (size_t)(qt * 64 + row) * S_ + kt * 64 + c4);
            *(uint4*)(Ks + row * AT_STRIDE + c4) = kv;
            *(uint4*)(Vs + row * AT_STRIDE + c4) = vv;
            *(uint4*)(Ms + row * AT_STRIDE + c4) = mv;
        }
        __syncthreads();

        // S = Q K^T
        float sc[8][4];
#pragma unroll
        for (int nt = 0; nt < 8; nt++)
#pragma unroll
            for (int q = 0; q < 4; q++) sc[nt][q] = 0.0f;
#pragma unroll
        for (int ks = 0; ks < 8; ks++) {
#pragma unroll
            for (int nt = 0; nt < 8; nt++) {
                uint32_t bb[2];
                bb[0] = Ks[(8 * nt + grp) * AT_STRIDE + 8 * ks + tig];
                bb[1] = Ks[(8 * nt + grp) * AT_STRIDE + 8 * ks + tig + 4];
                mma_16n8k8(sc[nt], aQ[ks], bb);
            }
        }

        if (kt == qt) {
#pragma unroll
            for (int nt = 0; nt < 8; nt++) {
                const int c0 = 8 * nt + 2 * tig;
                if (c0 > r0) sc[nt][0] = -1e30f;
                if (c0 + 1 > r0) sc[nt][1] = -1e30f;
                if (c0 > r1) sc[nt][2] = -1e30f;
                if (c0 + 1 > r1) sc[nt][3] = -1e30f;
            }
        }

        // online softmax (rows r0, r1); reduce across the 4-lane quad
        float mx0 = -1e30f, mx1 = -1e30f;
#pragma unroll
        for (int nt = 0; nt < 8; nt++) {
            mx0 = fmaxf(mx0, fmaxf(sc[nt][0], sc[nt][1]));
            mx1 = fmaxf(mx1, fmaxf(sc[nt][2], sc[nt][3]));
        }
        mx0 = fmaxf(mx0, __shfl_xor_sync(0xffffffffu, mx0, 1));
        mx0 = fmaxf(mx0, __shfl_xor_sync(0xffffffffu, mx0, 2));
        mx1 = fmaxf(mx1, __shfl_xor_sync(0xffffffffu, mx1, 1));
        mx1 = fmaxf(mx1, __shfl_xor_sync(0xffffffffu, mx1, 2));

        const float mn0 = fmaxf(mi0, mx0);
        const float mn1 = fmaxf(mi1, mx1);
        const float p0 = __expf(mi0 - mn0);
        const float p1 = __expf(mi1 - mn1);
        mi0 = mn0; mi1 = mn1;

        float s0 = 0.0f, s1 = 0.0f;
#pragma unroll
        for (int nt = 0; nt < 8; nt++) {
            sc[nt][0] = __expf(sc[nt][0] - mn0); s0 += sc[nt][0];
            sc[nt][1] = __expf(sc[nt][1] - mn0); s0 += sc[nt][1];
            sc[nt][2] = __expf(sc[nt][2] - mn1); s1 += sc[nt][2];
            sc[nt][3] = __expf(sc[nt][3] - mn1); s1 += sc[nt][3];
        }
        s0 += __shfl_xor_sync(0xffffffffu, s0, 1);
        s0 += __shfl_xor_sync(0xffffffffu, s0, 2);
        s1 += __shfl_xor_sync(0xffffffffu, s1, 1);
        s1 += __shfl_xor_sync(0xffffffffu, s1, 2);
        ls0 = ls0 * p0 + s0;
        ls1 = ls1 * p1 + s1;
#pragma unroll
        for (int nt = 0; nt < 8; nt++) {
            accPV[nt][0] *= p0; accPV[nt][1] *= p0;
            accPV[nt][2] *= p1; accPV[nt][3] *= p1;
        }

        // store P fragments to smem (warp-private rows), tf32-rounded
#pragma unroll
        for (int nt = 0; nt < 8; nt++) {
            uint2 v0 = {f2tf32(sc[nt][0]), f2tf32(sc[nt][1])};
            uint2 v1 = {f2tf32(sc[nt][2]), f2tf32(sc[nt][3])};
            *(uint2*)(Ps + r0 * AT_STRIDE + 8 * nt + 2 * tig) = v0;
            *(uint2*)(Ps + r1 * AT_STRIDE + 8 * nt + 2 * tig) = v1;
        }
        __syncwarp();

        // accPV += P V ; accMV += M V  (shared B fragments)
#pragma unroll
        for (int ks = 0; ks < 8; ks++) {
            uint32_t ap[4], am[4];
            ap[0] = Ps[r0 * AT_STRIDE + 8 * ks + tig];
            ap[1] = Ps[r1 * AT_STRIDE + 8 * ks + tig];
            ap[2] = Ps[r0 * AT_STRIDE + 8 * ks + tig + 4];
            ap[3] = Ps[r1 * AT_STRIDE + 8 * ks + tig + 4];
            am[0] = Ms[r0 * AT_STRIDE + 8 * ks + tig];
            am[1] = Ms[r1 * AT_STRIDE + 8 * ks + tig];
            am[2] = Ms[r0 * AT_STRIDE + 8 * ks + tig + 4];
            am[3] = Ms[r1 * AT_STRIDE + 8 * ks + tig + 4];
#pragma unroll
            for (int nt = 0; nt < 8; nt++) {
                uint32_t bb[2];
                bb[0] = Vs[(8 * ks + tig) * AT_STRIDE + 8 * nt + grp];
                bb[1] = Vs[(8 * ks + tig + 4) * AT_STRIDE + 8 * nt + grp];
                mma_16n8k8(accPV[nt], ap, bb);
                mma_16n8k8(accMV[nt], am, bb);
            }
        }
    }

    // epilogue: out = (1-l)*accPV/ls + l*accMV
    const float w1 = 1.0f - l1v;
    const float inv0 = w1 / ls0;
    const float inv1 = w1 / ls1;
    float* Og = g_att + ((size_t)(b * S_ + qt * 64)) * D_ + h * HD_;
#pragma unroll
    for (int nt = 0; nt < 8; nt++) {
        const int c0 = 8 * nt + 2 * tig;
        float2 o0, o1;
        o0.x = accPV[nt][0] * inv0 + l1v * accMV[nt][0];
        o0.y = accPV[nt][1] * inv0 + l1v * accMV[nt][1];
        o1.x = accPV[nt][2] * inv1 + l1v * accMV[nt][2];
        o1.y = accPV[nt][3] * inv1 + l1v * accMV[nt][3];
        *(float2*)(Og + (size_t)r0 * D_ + c0) = o0;
        *(float2*)(Og + (size_t)r1 * D_ + c0) = o1;
    }
}

// ---------------------------------------------------------------------------
// LayerNorm over D=512, one block (128 threads) per row. Reads g_att.
// ---------------------------------------------------------------------------
__global__ __launch_bounds__(128) void ln_kernel(
    const float* __restrict__ g, const float* __restrict__ bb,
    float* __restrict__ out)
{
    __shared__ float r1[4], r2[4];
    const int row = blockIdx.x;
    const int tid = threadIdx.x;
    const float* xr = g_att + (size_t)row * D_;
    float4 v = *(const float4*)(xr + tid * 4);
    float s = v.x + v.y + v.z + v.w;
    float sq = v.x * v.x + v.y * v.y + v.z * v.z + v.w * v.w;
#pragma unroll
    for (int m = 16; m >= 1; m >>= 1) {
        s += __shfl_xor_sync(0xffffffffu, s, m);
        sq += __shfl_xor_sync(0xffffffffu, sq, m);
    }
    if ((tid & 31) == 0) { r1[tid >> 5] = s; r2[tid >> 5] = sq; }
    __syncthreads();
    s = r1[0] + r1[1] + r1[2] + r1[3];
    sq = r2[0] + r2[1] + r2[2] + r2[3];
    const float mu = s * (1.0f / 512.0f);
    const float var = sq * (1.0f / 512.0f) - mu * mu;
    const float rstd = rsqrtf(var + 1e-5f);
    float4 gg = *(const float4*)(g + tid * 4);
    float4 bv = *(const float4*)(bb + tid * 4);
    float4 o;
    o.x = (v.x - mu) * rstd * gg.x + bv.x;
    o.y = (v.y - mu) * rstd * gg.y + bv.y;
    o.z = (v.z - mu) * rstd * gg.z + bv.z;
    o.w = (v.w - mu) * rstd * gg.w + bv.w;
    *(float4*)(out + (size_t)row * D_ + tid * 4) = o;
}

// ---------------------------------------------------------------------------
extern "C" void kernel_launch(void* const* d_in, const int* in_sizes, int n_in,
                              void* d_out, int out_size)
{
    (void)in_sizes; (void)n_in; (void)out_size;
    const float* inputs = (const float*)d_in[1];
    const float* ren    = (const float*)d_in[2];
    const float* tsp    = (const float*)d_in[3];
    const float* Wq = (const float*)d_in[5];
    const float* bq = (const float*)d_in[6];
    const float* Wk = (const float*)d_in[7];
    const float* bk = (const float*)d_in[8];
    const float* Wv = (const float*)d_in[9];
    const float* bv = (const float*)d_in[10];
    const float* Wo = (const float*)d_in[11];
    const float* bo = (const float*)d_in[12];
    const float* W1 = (const float*)d_in[13];
    const float* b1 = (const float*)d_in[14];
    const float* lng = (const float*)d_in[15];
    const float* lnb = (const float*)d_in[16];
    const float* l1  = (const float*)d_in[17];
    float* out = (float*)d_out;

    cudaFuncSetAttribute(tgemm_kernel<1, 0, 0>, cudaFuncAttributeMaxDynamicSharedMemorySize, TG_SMEM);
    cudaFuncSetAttribute(tgemm_kernel<1, 0, 1>, cudaFuncAttributeMaxDynamicSharedMemorySize, TG_SMEM);
    cudaFuncSetAttribute(tgemm_kernel<1, 0, 2>, cudaFuncAttributeMaxDynamicSharedMemorySize, TG_SMEM);
    cudaFuncSetAttribute(tgemm_kernel<0, 1, 4>, cudaFuncAttributeMaxDynamicSharedMemorySize, TG_SMEM);
    cudaFuncSetAttribute(tgemm_kernel<2, 2, 3>, cudaFuncAttributeMaxDynamicSharedMemorySize, TG_SMEM);
    cudaFuncSetAttribute(attn_kernel, cudaFuncAttributeMaxDynamicSharedMemorySize, AT_SMEM);

    const dim3 ggrid(NROWS / 128, D_ / 128);

    // QKV projections (Q pre-scaled by 1/8; outputs tf32-rounded)
    tgemm_kernel<1, 0, 0><<<ggrid, 256, TG_SMEM>>>(inputs, Wq, bq, 0.125f);
    tgemm_kernel<1, 0, 1><<<ggrid, 256, TG_SMEM>>>(inputs, Wk, bk, 1.0f);
    tgemm_kernel<1, 0, 2><<<ggrid, 256, TG_SMEM>>>(inputs, Wv, bv, 1.0f);

    // mem-attention probabilities (head-independent, tf32-rounded)
    mem_kernel<<<NROWS, 256>>>(ren, tsp);

    // blended flash attention (tensor-core) -> g_att
    attn_kernel<<<dim3(B_ * H_, S_ / 64), 128, AT_SMEM>>>(l1);

    // Wo projection: g_att @ Wo^T + bo -> g_o2
    tgemm_kernel<0, 1, 4><<<ggrid, 256, TG_SMEM>>>(nullptr, Wo, bo, 1.0f);
    // FFN + residual: g_o2 + g_o2 @ W1^T + b1 -> g_att
    tgemm_kernel<2, 2, 3><<<ggrid, 256, TG_SMEM>>>(nullptr, W1, b1, 1.0f);
    // LayerNorm -> d_out
    ln_kernel<<<NROWS, 128>>>(lng, lnb, out);
}

// round 15
// speedup vs baseline: 3.9728x; 1.5005x over previous
#include <cuda_runtime.h>
#include <cuda_fp16.h>
#include <cstdint>

#define B_ 8
#define S_ 1024
#define D_ 512
#define H_ 8
#define HD_ 64
#define NROWS (B_ * S_)   // 8192

// ---------------- scratch (static device globals; no runtime allocation) ----
__device__ __half g_qh[B_ * H_ * S_ * HD_];   // 8 MB, [bh][s][hd], pre-scaled 1/8
__device__ __half g_kh[B_ * H_ * S_ * HD_];   // 8 MB, [bh][s][hd]
__device__ __half g_vt[B_ * H_ * HD_ * S_];   // 8 MB, TRANSPOSED [bh][hd][s]
__device__ __half g_memh[B_ * S_ * S_];       // 16 MB, normalized mem-attn probs
__device__ float g_att[NROWS * D_];           // 16 MB (attn out, later FFN out)
__device__ float g_o2[NROWS * D_];            // 16 MB (Wo out)

// ========================== mma.sync fp16 helpers ==========================
__device__ __forceinline__ uint32_t f2h2(float lo, float hi) {
    __half2 h = __floats2half2_rn(lo, hi);
    return *reinterpret_cast<uint32_t*>(&h);
}

__device__ __forceinline__ void mma_f16(float* c, const uint32_t* a,
                                        const uint32_t* b) {
    asm volatile(
        "mma.sync.aligned.m16n8k16.row.col.f32.f16.f16.f32 "
        "{%0,%1,%2,%3}, {%4,%5,%6,%7}, {%8,%9}, {%0,%1,%2,%3};"
        : "+f"(c[0]), "+f"(c[1]), "+f"(c[2]), "+f"(c[3])
        : "r"(a[0]), "r"(a[1]), "r"(a[2]), "r"(a[3]), "r"(b[0]), "r"(b[1]));
}

// ---------------------------------------------------------------------------
// Shared GEMM mainloop (fp32 inputs staged as fp16). 128x128 tile, 8 warps
// each 64x32, BK=32 (2 k16 steps), double-buffered. Conflict-free stride 20.
// Epi is a PLAIN lambda (implicitly device; no --extended-lambda needed).
// ---------------------------------------------------------------------------
#define TG_ST 20
#define TG_BUF (128 * TG_ST)

template <typename Epi>
__device__ __forceinline__ void gemm_core(const float* __restrict__ X,
                                          const float* __restrict__ W,
                                          int n0, int m0, Epi epi)
{
    __shared__ uint32_t sm[4 * TG_BUF];   // A0,B0,A1,B1 = 40960 B
    const int tid = threadIdx.x;
    const int fr = tid >> 3;
    const int fc = tid & 7;
    const float* Ap = X + (size_t)(n0 + fr) * D_ + fc * 4;
    const float* Wp = W + (size_t)(m0 + fr) * D_ + fc * 4;

    const int wid = tid >> 5;
    const int lane = tid & 31;
    const int grp = lane >> 2;
    const int tig = lane & 3;
    const int wy = wid & 1;
    const int wx = wid >> 1;

    float acc[4][4][4];
#pragma unroll
    for (int i = 0; i < 4; i++)
#pragma unroll
        for (int j = 0; j < 4; j++)
#pragma unroll
            for (int q = 0; q < 4; q++) acc[i][j][q] = 0.0f;

    float4 ra[4], rb[4];
    auto gload = [&](int c) {
        const int kb = c * 32;
#pragma unroll
        for (int g = 0; g < 4; g++) {
            ra[g] = *(const float4*)(Ap + kb + (size_t)g * 32 * D_);
            rb[g] = *(const float4*)(Wp + kb + (size_t)g * 32 * D_);
        }
    };
    auto sts = [&](int c) {
        uint32_t* bufA = sm + (c & 1) * 2 * TG_BUF;
        uint32_t* bufB = bufA + TG_BUF;
#pragma unroll
        for (int g = 0; g < 4; g++) {
            const uint32_t off = (uint32_t)(g * 32 + fr) * TG_ST + fc * 2;
            uint2 a2 = {f2h2(ra[g].x, ra[g].y), f2h2(ra[g].z, ra[g].w)};
            uint2 b2 = {f2h2(rb[g].x, rb[g].y), f2h2(rb[g].z, rb[g].w)};
            *(uint2*)(bufA + off) = a2;
            *(uint2*)(bufB + off) = b2;
        }
    };
    auto compute = [&](int c) {
        const uint32_t* A = sm + (c & 1) * 2 * TG_BUF;
        const uint32_t* Bm = A + TG_BUF;
#pragma unroll
        for (int ks = 0; ks < 2; ks++) {
            const int kk = ks * 8 + tig;
            uint32_t af[4][4], bf[4][2];
#pragma unroll
            for (int rt = 0; rt < 4; rt++) {
                const int r = wy * 64 + rt * 16 + grp;
                af[rt][0] = A[r * TG_ST + kk];
                af[rt][1] = A[(r + 8) * TG_ST + kk];
                af[rt][2] = A[r * TG_ST + kk + 4];
                af[rt][3] = A[(r + 8) * TG_ST + kk + 4];
            }
#pragma unroll
            for (int ct = 0; ct < 4; ct++) {
                const int j = wx * 32 + ct * 8 + grp;
                bf[ct][0] = Bm[j * TG_ST + kk];
                bf[ct][1] = Bm[j * TG_ST + kk + 4];
            }
#pragma unroll
            for (int rt = 0; rt < 4; rt++)
#pragma unroll
                for (int ct = 0; ct < 4; ct++)
                    mma_f16(acc[rt][ct], af[rt], bf[ct]);
        }
    };

    gload(0);
    sts(0);
    __syncthreads();
    for (int c = 0; c < 16; c++) {
        if (c < 15) gload(c + 1);
        compute(c);
        if (c < 15) sts(c + 1);
        __syncthreads();
    }

#pragma unroll
    for (int rt = 0; rt < 4; rt++) {
        const int n_lo = n0 + wy * 64 + rt * 16 + grp;
#pragma unroll
        for (int ct = 0; ct < 4; ct++) {
            const int m2 = m0 + wx * 32 + ct * 8 + 2 * tig;
            epi(n_lo, n_lo + 8, m2, acc[rt][ct]);
        }
    }
}

// ---------------------------------------------------------------------------
// QKV projections fused: grid.z selects Q/K/V. Outputs fp16 (V transposed).
// ---------------------------------------------------------------------------
__global__ __launch_bounds__(256, 1)
void qkv_kernel(const float* __restrict__ X,
                const float* __restrict__ Wq, const float* __restrict__ Wk,
                const float* __restrict__ Wv, const float* __restrict__ bq,
                const float* __restrict__ bk, const float* __restrict__ bv)
{
    const int z = blockIdx.z;
    const float* W = (z == 0) ? Wq : (z == 1) ? Wk : Wv;
    const float* bias = (z == 0) ? bq : (z == 1) ? bk : bv;
    const float scale = (z == 0) ? 0.125f : 1.0f;
    const int n0 = blockIdx.x * 128;
    const int m0 = blockIdx.y * 128;

    gemm_core(X, W, n0, m0,
        [&](int n_lo, int n_hi, int m2, const float* c) {
            const float2 bv2 = *(const float2*)(bias + m2);
            const float lx = (c[0] + bv2.x) * scale;
            const float ly = (c[1] + bv2.y) * scale;
            const float hx = (c[2] + bv2.x) * scale;
            const float hy = (c[3] + bv2.y) * scale;
            const int h = m2 >> 6, hd = m2 & 63;
            const int blo = n_lo >> 10, slo = n_lo & 1023;
            const int bhi = n_hi >> 10, shi = n_hi & 1023;
            if (z < 2) {
                __half* out = (z == 0) ? g_qh : g_kh;
                const size_t olo = ((size_t)((blo * H_ + h) * S_ + slo)) * HD_ + hd;
                const size_t ohi = ((size_t)((bhi * H_ + h) * S_ + shi)) * HD_ + hd;
                *(uint32_t*)(out + olo) = f2h2(lx, ly);
                *(uint32_t*)(out + ohi) = f2h2(hx, hy);
            } else {
                // transposed store: g_vt[bh][hd][s]
                const size_t base_lo = ((size_t)(blo * H_ + h)) * HD_ * S_;
                const size_t base_hi = ((size_t)(bhi * H_ + h)) * HD_ * S_;
                g_vt[base_lo + (size_t)hd * S_ + slo] = __float2half_rn(lx);
                g_vt[base_lo + (size_t)(hd + 1) * S_ + slo] = __float2half_rn(ly);
                g_vt[base_hi + (size_t)hd * S_ + shi] = __float2half_rn(hx);
                g_vt[base_hi + (size_t)(hd + 1) * S_ + shi] = __float2half_rn(hy);
            }
        });
}

// ---------------------------------------------------------------------------
// Output GEMMs: MODE 0 = Wo (g_att -> g_o2), MODE 2 = FFN+resid (g_o2 -> g_att)
// ---------------------------------------------------------------------------
template <int MODE>
__global__ __launch_bounds__(256, 1)
void tgemm_kernel(const float* __restrict__ W, const float* __restrict__ bias)
{
    const float* X = (MODE == 0) ? g_att : g_o2;
    float* out = (MODE == 0) ? g_o2 : g_att;
    const int n0 = blockIdx.x * 128;
    const int m0 = blockIdx.y * 128;

    gemm_core(X, W, n0, m0,
        [&](int n_lo, int n_hi, int m2, const float* c) {
            const float2 bv2 = *(const float2*)(bias + m2);
            float2 lo = {c[0] + bv2.x, c[1] + bv2.y};
            float2 hi = {c[2] + bv2.x, c[3] + bv2.y};
            const size_t off_lo = (size_t)n_lo * D_ + m2;
            const size_t off_hi = (size_t)n_hi * D_ + m2;
            if (MODE == 2) {
                float2 rlo = *(const float2*)(g_o2 + off_lo);
                float2 rhi = *(const float2*)(g_o2 + off_hi);
                lo.x += rlo.x; lo.y += rlo.y;
                hi.x += rhi.x; hi.y += rhi.y;
            }
            *(float2*)(out + off_lo) = lo;
            *(float2*)(out + off_hi) = hi;
        });
}

// ---------------------------------------------------------------------------
// mem-attention: softmax_k over [ log10(ren+1) + exp(-|ts|) ], causal, per (b,q)
// Output fp16 probs (consumed only by tensor-core MV GEMM).
// ---------------------------------------------------------------------------
__global__ __launch_bounds__(256) void mem_kernel(
    const float* __restrict__ ren, const float* __restrict__ ts)
{
    __shared__ float red[8];
    const int bq = blockIdx.x;
    const int q = bq & (S_ - 1);
    const float* rp = ren + (size_t)bq * S_;
    const float* tp = ts + (size_t)bq * S_;
    __half* op = g_memh + (size_t)bq * S_;
    const int tid = threadIdx.x;
    const int k0 = tid * 4;

    float v[4];
    if (k0 <= q) {
        float4 rr = *(const float4*)(rp + k0);
        float4 tt = *(const float4*)(tp + k0);
        float rv[4] = {rr.x, rr.y, rr.z, rr.w};
        float tv[4] = {tt.x, tt.y, tt.z, tt.w};
#pragma unroll
        for (int j = 0; j < 4; j++)
            v[j] = (k0 + j <= q)
                       ? (__log10f(rv[j] + 1.0f) + __expf(-fabsf(tv[j])))
                       : -1e30f;
    } else {
        v[0] = v[1] = v[2] = v[3] = -1e30f;
    }

    float mx = fmaxf(fmaxf(v[0], v[1]), fmaxf(v[2], v[3]));
#pragma unroll
    for (int m = 16; m >= 1; m >>= 1)
        mx = fmaxf(mx, __shfl_xor_sync(0xffffffffu, mx, m));
    if ((tid & 31) == 0) red[tid >> 5] = mx;
    __syncthreads();
    if (tid < 32) {
        float t = (tid < 8) ? red[tid] : -1e30f;
#pragma unroll
        for (int m = 4; m >= 1; m >>= 1)
            t = fmaxf(t, __shfl_xor_sync(0xffffffffu, t, m));
        if (tid == 0) red[0] = t;
    }
    __syncthreads();
    mx = red[0];
    __syncthreads();

    float e[4];
    float s = 0.0f;
#pragma unroll
    for (int j = 0; j < 4; j++) { e[j] = __expf(v[j] - mx); s += e[j]; }
#pragma unroll
    for (int m = 16; m >= 1; m >>= 1)
        s += __shfl_xor_sync(0xffffffffu, s, m);
    if ((tid & 31) == 0) red[tid >> 5] = s;
    __syncthreads();
    if (tid < 32) {
        float t = (tid < 8) ? red[tid] : 0.0f;
#pragma unroll
        for (int m = 4; m >= 1; m >>= 1)
            t += __shfl_xor_sync(0xffffffffu, t, m);
        if (tid == 0) red[0] = t;
    }
    __syncthreads();
    const float inv = 1.0f / red[0];

    uint2 o;
    o.x = f2h2(e[0] * inv, e[1] * inv);
    o.y = f2h2(e[2] * inv, e[3] * inv);
    *(uint2*)(op + k0) = o;
}

// ---------------------------------------------------------------------------
// Flash attention + mem blend, mma.sync fp16 m16n8k16.
// 128 threads (4 warps); warp w owns q-rows [w*16, w*16+16).
// P fragments built in-register from QK^T C-fragments (no smem round-trip).
// ---------------------------------------------------------------------------
#define AT_ST 36   // u32 stride per 64-half row (conflict-free: 4*grp+tig)

__global__ __launch_bounds__(128) void attn_kernel(const float* __restrict__ l1p)
{
    __shared__ uint32_t Ks[64 * AT_ST];   // K tile [key][hd] halfs
    __shared__ uint32_t Vs[64 * AT_ST];   // V tile [hd][key] halfs
    __shared__ uint32_t Ms[64 * AT_ST];   // M tile [qrow][key] halfs

    const int bh = blockIdx.x;
    const int qt = (int)gridDim.y - 1 - (int)blockIdx.y;   // heavy blocks first
    const int b = bh >> 3;
    const int tid = threadIdx.x;
    const int wid = tid >> 5;
    const int lane = tid & 31;
    const int grp = lane >> 2;
    const int tig = lane & 3;
    const int r0 = wid * 16 + grp;
    const int r1 = r0 + 8;
    const float l1v = *l1p;

    const uint32_t* Qg = (const uint32_t*)g_qh + ((size_t)bh * S_ + (size_t)qt * 64) * 32;
    const uint4* K4 = (const uint4*)g_kh + (size_t)bh * S_ * 8;
    const uint4* V4 = (const uint4*)g_vt + (size_t)bh * HD_ * 128;
    const uint4* M4 = (const uint4*)g_memh + (size_t)b * S_ * 128;

    // Q A-fragments, loop invariant (4 k16 steps cover HD=64)
    uint32_t aQ[4][4];
#pragma unroll
    for (int kk = 0; kk < 4; kk++) {
        aQ[kk][0] = Qg[r0 * 32 + 8 * kk + tig];
        aQ[kk][1] = Qg[r1 * 32 + 8 * kk + tig];
        aQ[kk][2] = Qg[r0 * 32 + 8 * kk + tig + 4];
        aQ[kk][3] = Qg[r1 * 32 + 8 * kk + tig + 4];
    }

    float mi0 = -1e30f, mi1 = -1e30f, ls0 = 0.0f, ls1 = 0.0f;
    float accPV[8][4], accMV[8][4];
#pragma unroll
    for (int nt = 0; nt < 8; nt++)
#pragma unroll
        for (int q = 0; q < 4; q++) { accPV[nt][q] = 0.0f; accMV[nt][q] = 0.0f; }

    for (int kt = 0; kt <= qt; kt++) {
        __syncthreads();
#pragma unroll
        for (int p = 0; p < 4; p++) {
            const int idx = tid + p * 128;       // 512 uint4 per matrix
            const int row = idx >> 3;
            const int c = idx & 7;
            uint4 kv = K4[(size_t)(kt * 64 + row) * 8 + c];
            uint4 vv = V4[(size_t)row * 128 + kt * 8 + c];
            uint4 mv = M4[(size_t)(qt * 64 + row) * 128 + kt * 8 + c];
            *(uint4*)(Ks + row * AT_ST + c * 4) = kv;
            *(uint4*)(Vs + row * AT_ST + c * 4) = vv;
            *(uint4*)(Ms + row * AT_ST + c * 4) = mv;
        }
        __syncthreads();

        // S = Q K^T  (4 k16 steps x 8 n-tiles)
        float sc[8][4];
#pragma unroll
        for (int nt = 0; nt < 8; nt++)
#pragma unroll
            for (int q = 0; q < 4; q++) sc[nt][q] = 0.0f;
#pragma unroll
        for (int kk = 0; kk < 4; kk++) {
#pragma unroll
            for (int nt = 0; nt < 8; nt++) {
                uint32_t bb[2];
                bb[0] = Ks[(8 * nt + grp) * AT_ST + 8 * kk + tig];
                bb[1] = Ks[(8 * nt + grp) * AT_ST + 8 * kk + tig + 4];
                mma_f16(sc[nt], aQ[kk], bb);
            }
        }

        if (kt == qt) {
#pragma unroll
            for (int nt = 0; nt < 8; nt++) {
                const int c0 = 8 * nt + 2 * tig;
                if (c0 > r0) sc[nt][0] = -1e30f;
                if (c0 + 1 > r0) sc[nt][1] = -1e30f;
                if (c0 > r1) sc[nt][2] = -1e30f;
                if (c0 + 1 > r1) sc[nt][3] = -1e30f;
            }
        }

        // online softmax (rows r0, r1); reduce across the 4-lane quad
        float mx0 = -1e30f, mx1 = -1e30f;
#pragma unroll
        for (int nt = 0; nt < 8; nt++) {
            mx0 = fmaxf(mx0, fmaxf(sc[nt][0], sc[nt][1]));
            mx1 = fmaxf(mx1, fmaxf(sc[nt][2], sc[nt][3]));
        }
        mx0 = fmaxf(mx0, __shfl_xor_sync(0xffffffffu, mx0, 1));
        mx0 = fmaxf(mx0, __shfl_xor_sync(0xffffffffu, mx0, 2));
        mx1 = fmaxf(mx1, __shfl_xor_sync(0xffffffffu, mx1, 1));
        mx1 = fmaxf(mx1, __shfl_xor_sync(0xffffffffu, mx1, 2));

        const float mn0 = fmaxf(mi0, mx0);
        const float mn1 = fmaxf(mi1, mx1);
        const float p0 = __expf(mi0 - mn0);
        const float p1 = __expf(mi1 - mn1);
        mi0 = mn0; mi1 = mn1;

        float s0 = 0.0f, s1 = 0.0f;
#pragma unroll
        for (int nt = 0; nt < 8; nt++) {
            sc[nt][0] = __expf(sc[nt][0] - mn0); s0 += sc[nt][0];
            sc[nt][1] = __expf(sc[nt][1] - mn0); s0 += sc[nt][1];
            sc[nt][2] = __expf(sc[nt][2] - mn1); s1 += sc[nt][2];
            sc[nt][3] = __expf(sc[nt][3] - mn1); s1 += sc[nt][3];
        }
        s0 += __shfl_xor_sync(0xffffffffu, s0, 1);
        s0 += __shfl_xor_sync(0xffffffffu, s0, 2);
        s1 += __shfl_xor_sync(0xffffffffu, s1, 1);
        s1 += __shfl_xor_sync(0xffffffffu, s1, 2);
        ls0 = ls0 * p0 + s0;
        ls1 = ls1 * p1 + s1;
#pragma unroll
        for (int nt = 0; nt < 8; nt++) {
            accPV[nt][0] *= p0; accPV[nt][1] *= p0;
            accPV[nt][2] *= p1; accPV[nt][3] *= p1;
        }

        // accPV += P V ; accMV += M V — P A-frags packed from C-frags in regs
#pragma unroll
        for (int ks = 0; ks < 4; ks++) {
            uint32_t ap[4], am[4];
            ap[0] = f2h2(sc[2 * ks][0], sc[2 * ks][1]);
            ap[1] = f2h2(sc[2 * ks][2], sc[2 * ks][3]);
            ap[2] = f2h2(sc[2 * ks + 1][0], sc[2 * ks + 1][1]);
            ap[3] = f2h2(sc[2 * ks + 1][2], sc[2 * ks + 1][3]);
            am[0] = Ms[r0 * AT_ST + 8 * ks + tig];
            am[1] = Ms[r1 * AT_ST + 8 * ks + tig];
            am[2] = Ms[r0 * AT_ST + 8 * ks + tig + 4];
            am[3] = Ms[r1 * AT_ST + 8 * ks + tig + 4];
#pragma unroll
            for (int nt = 0; nt < 8; nt++) {
                uint32_t bb[2];
                bb[0] = Vs[(8 * nt + grp) * AT_ST + 8 * ks + tig];
                bb[1] = Vs[(8 * nt + grp) * AT_ST + 8 * ks + tig + 4];
                mma_f16(accPV[nt], ap, bb);
                mma_f16(accMV[nt], am, bb);
            }
        }
    }

    // epilogue: out = (1-l)*accPV/ls + l*accMV
    const float w1 = 1.0f - l1v;
    const float inv0 = w1 / ls0;
    const float inv1 = w1 / ls1;
    const int h = bh & 7;
    float* Og = g_att + ((size_t)(b * S_ + qt * 64)) * D_ + h * HD_;
#pragma unroll
    for (int nt = 0; nt < 8; nt++) {
        const int c0 = 8 * nt + 2 * tig;
        float2 o0, o1;
        o0.x = accPV[nt][0] * inv0 + l1v * accMV[nt][0];
        o0.y = accPV[nt][1] * inv0 + l1v * accMV[nt][1];
        o1.x = accPV[nt][2] * inv1 + l1v * accMV[nt][2];
        o1.y = accPV[nt][3] * inv1 + l1v * accMV[nt][3];
        *(float2*)(Og + (size_t)r0 * D_ + c0) = o0;
        *(float2*)(Og + (size_t)r1 * D_ + c0) = o1;
    }
}

// ---------------------------------------------------------------------------
// LayerNorm over D=512, one block (128 threads) per row. Reads g_att.
// ---------------------------------------------------------------------------
__global__ __launch_bounds__(128) void ln_kernel(
    const float* __restrict__ g, const float* __restrict__ bb,
    float* __restrict__ out)
{
    __shared__ float r1[4], r2[4];
    const int row = blockIdx.x;
    const int tid = threadIdx.x;
    const float* xr = g_att + (size_t)row * D_;
    float4 v = *(const float4*)(xr + tid * 4);
    float s = v.x + v.y + v.z + v.w;
    float sq = v.x * v.x + v.y * v.y + v.z * v.z + v.w * v.w;
#pragma unroll
    for (int m = 16; m >= 1; m >>= 1) {
        s += __shfl_xor_sync(0xffffffffu, s, m);
        sq += __shfl_xor_sync(0xffffffffu, sq, m);
    }
    if ((tid & 31) == 0) { r1[tid >> 5] = s; r2[tid >> 5] = sq; }
    __syncthreads();
    s = r1[0] + r1[1] + r1[2] + r1[3];
    sq = r2[0] + r2[1] + r2[2] + r2[3];
    const float mu = s * (1.0f / 512.0f);
    const float var = sq * (1.0f / 512.0f) - mu * mu;
    const float rstd = rsqrtf(var + 1e-5f);
    float4 gg = *(const float4*)(g + tid * 4);
    float4 bv = *(const float4*)(bb + tid * 4);
    float4 o;
    o.x = (v.x - mu) * rstd * gg.x + bv.x;
    o.y = (v.y - mu) * rstd * gg.y + bv.y;
    o.z = (v.z - mu) * rstd * gg.z + bv.z;
    o.w = (v.w - mu) * rstd * gg.w + bv.w;
    *(float4*)(out + (size_t)row * D_ + tid * 4) = o;
}

// ---------------------------------------------------------------------------
extern "C" void kernel_launch(void* const* d_in, const int* in_sizes, int n_in,
                              void* d_out, int out_size)
{
    (void)in_sizes; (void)n_in; (void)out_size;
    const float* inputs = (const float*)d_in[1];
    const float* ren    = (const float*)d_in[2];
    const float* tsp    = (const float*)d_in[3];
    const float* Wq = (const float*)d_in[5];
    const float* bq = (const float*)d_in[6];
    const float* Wk = (const float*)d_in[7];
    const float* bk = (const float*)d_in[8];
    const float* Wv = (const float*)d_in[9];
    const float* bv = (const float*)d_in[10];
    const float* Wo = (const float*)d_in[11];
    const float* bo = (const float*)d_in[12];
    const float* W1 = (const float*)d_in[13];
    const float* b1 = (const float*)d_in[14];
    const float* lng = (const float*)d_in[15];
    const float* lnb = (const float*)d_in[16];
    const float* l1  = (const float*)d_in[17];
    float* out = (float*)d_out;

    const dim3 gq(NROWS / 128, D_ / 128, 3);
    const dim3 gg(NROWS / 128, D_ / 128);

    // QKV projections fused (fp16 outputs; V transposed; Q pre-scaled 1/8)
    qkv_kernel<<<gq, 256>>>(inputs, Wq, Wk, Wv, bq, bk, bv);

    // mem-attention probabilities (head-independent, fp16)
    mem_kernel<<<NROWS, 256>>>(ren, tsp);

    // blended flash attention (fp16 tensor) -> g_att
    attn_kernel<<<dim3(B_ * H_, S_ / 64), 128>>>(l1);

    // Wo projection: g_att @ Wo^T + bo -> g_o2
    tgemm_kernel<0><<<gg, 256>>>(Wo, bo);
    // FFN + residual: g_o2 + g_o2 @ W1^T + b1 -> g_att
    tgemm_kernel<2><<<gg, 256>>>(W1, b1);
    // LayerNorm -> d_out
    ln_kernel<<<NROWS, 128>>>(lng, lnb, out);
}

// round 17
// speedup vs baseline: 4.8675x; 1.2252x over previous
#include <cuda_runtime.h>
#include <cuda_fp16.h>
#include <cstdint>

#define B_ 8
#define S_ 1024
#define D_ 512
#define H_ 8
#define HD_ 64
#define NROWS (B_ * S_)   // 8192
#define WSLICE (D_ * D_)  // 262144

// ---------------- scratch (static device globals; no runtime allocation) ----
__device__ __half g_xh[NROWS * D_];           // 8 MB, inputs as fp16
__device__ __half g_wh[5 * WSLICE];           // 2.6 MB, Wq,Wk,Wv,Wo,W1 as fp16
__device__ __half g_qh[B_ * H_ * S_ * HD_];   // 8 MB, [bh][s][hd], pre-scaled 1/8
__device__ __half g_kh[B_ * H_ * S_ * HD_];   // 8 MB, [bh][s][hd]
__device__ __half g_vt[B_ * H_ * HD_ * S_];   // 8 MB, TRANSPOSED [bh][hd][s]
__device__ __half g_memh[B_ * S_ * S_];       // 16 MB, normalized mem-attn probs
__device__ __half g_atth[NROWS * D_];         // 8 MB, attn out (fp16, Wo input)
__device__ float g_o2[NROWS * D_];            // 16 MB, Wo out fp32 (residual)
__device__ __half g_o2h[NROWS * D_];          // 8 MB, Wo out fp16 (FFN input)
__device__ float g_att[NROWS * D_];           // 16 MB, FFN out fp32 (LN input)

// ========================== helpers ========================================
__device__ __forceinline__ uint32_t f2h2(float lo, float hi) {
    __half2 h = __floats2half2_rn(lo, hi);
    return *reinterpret_cast<uint32_t*>(&h);
}

__device__ __forceinline__ uint32_t smem_u32(const void* p) {
    uint32_t a;
    asm("{ .reg .u64 t; cvta.to.shared.u64 t, %1; cvt.u32.u64 %0, t; }"
        : "=r"(a) : "l"(p));
    return a;
}

__device__ __forceinline__ void mma_f16(float* c, const uint32_t* a,
                                        const uint32_t* b) {
    asm volatile(
        "mma.sync.aligned.m16n8k16.row.col.f32.f16.f16.f32 "
        "{%0,%1,%2,%3}, {%4,%5,%6,%7}, {%8,%9}, {%0,%1,%2,%3};"
        : "+f"(c[0]), "+f"(c[1]), "+f"(c[2]), "+f"(c[3])
        : "r"(a[0]), "r"(a[1]), "r"(a[2]), "r"(a[3]), "r"(b[0]), "r"(b[1]));
}

#define CP_ASYNC16(dst, src) \
    asm volatile("cp.async.cg.shared.global [%0], [%1], 16;" \
                 :: "r"(dst), "l"(src))
#define CP_COMMIT() asm volatile("cp.async.commit_group;" ::: "memory")

// ---------------------------------------------------------------------------
// fp32 -> fp16 converters
// ---------------------------------------------------------------------------
__global__ __launch_bounds__(256) void cvt_in_kernel(const float* __restrict__ s)
{
    const int i = (blockIdx.x * 256 + threadIdx.x) * 4;
    float4 v = *(const float4*)(s + i);
    uint2 o = {f2h2(v.x, v.y), f2h2(v.z, v.w)};
    *(uint2*)(g_xh + i) = o;
}

__global__ __launch_bounds__(256) void cvt_w_kernel(
    const float* __restrict__ w0, const float* __restrict__ w1,
    const float* __restrict__ w2, const float* __restrict__ w3,
    const float* __restrict__ w4)
{
    const int z = blockIdx.y;
    const float* s = (z == 0) ? w0 : (z == 1) ? w1 : (z == 2) ? w2
                    : (z == 3) ? w3 : w4;
    const int i = (blockIdx.x * 256 + threadIdx.x) * 4;
    float4 v = *(const float4*)(s + i);
    uint2 o = {f2h2(v.x, v.y), f2h2(v.z, v.w)};
    *(uint2*)(g_wh + (size_t)z * WSLICE + i) = o;
}

// ---------------------------------------------------------------------------
// GEMM mainloop: fp16 X [n][512], fp16 W [m][512]; 128x128 tile, 8 warps
// each 64x32; BK=32; 4-stage cp.async pipeline; 2 CTAs/SM.
// ---------------------------------------------------------------------------
#define TG_ST 20                      // u32 stride per 32-half row
#define TG_STAGE (128 * TG_ST)        // u32 per matrix per stage (10 KB)
#define TG_SMEM (4 * 2 * TG_STAGE * 4)  // 81920 B

template <typename Epi>
__device__ __forceinline__ void gemm_core(const __half* __restrict__ X,
                                          const __half* __restrict__ W,
                                          int n0, int m0, Epi epi)
{
    extern __shared__ uint32_t smu[];
    const uint32_t sb = smem_u32(smu);
    const int tid = threadIdx.x;
    const int wid = tid >> 5;
    const int lane = tid & 31;
    const int grp = lane >> 2;
    const int tig = lane & 3;
    const int wy = wid & 1;
    const int wx = wid >> 1;

    float acc[4][4][4];
#pragma unroll
    for (int i = 0; i < 4; i++)
#pragma unroll
        for (int j = 0; j < 4; j++)
#pragma unroll
            for (int q = 0; q < 4; q++) acc[i][j][q] = 0.0f;

    // per-thread cp.async assignment: 2 slots x (A,B); slot = row*4+quad
    const int s0r = tid >> 2, s0q = tid & 3;            // slots 0..255
    const int s1r = 64 + s0r, s1q = s0q;                // slots 256..511
    const __half* Xa0 = X + (size_t)(n0 + s0r) * D_ + s0q * 8;
    const __half* Xa1 = X + (size_t)(n0 + s1r) * D_ + s1q * 8;
    const __half* Wb0 = W + (size_t)(m0 + s0r) * D_ + s0q * 8;
    const __half* Wb1 = W + (size_t)(m0 + s1r) * D_ + s1q * 8;
    const uint32_t o0 = (uint32_t)(s0r * TG_ST + s0q * 4) * 4;
    const uint32_t o1 = (uint32_t)(s1r * TG_ST + s1q * 4) * 4;

    auto issue = [&](int c) {
        const uint32_t baseA = sb + (uint32_t)((c & 3) * 2 * TG_STAGE) * 4;
        const uint32_t baseB = baseA + TG_STAGE * 4;
        const int kb = c * 32;
        CP_ASYNC16(baseA + o0, Xa0 + kb);
        CP_ASYNC16(baseA + o1, Xa1 + kb);
        CP_ASYNC16(baseB + o0, Wb0 + kb);
        CP_ASYNC16(baseB + o1, Wb1 + kb);
        CP_COMMIT();
    };

    auto compute = [&](int c) {
        const uint32_t* A = smu + (c & 3) * 2 * TG_STAGE;
        const uint32_t* Bm = A + TG_STAGE;
#pragma unroll
        for (int ks = 0; ks < 2; ks++) {
            const int kk = ks * 8 + tig;
            uint32_t af[4][4], bf[4][2];
#pragma unroll
            for (int rt = 0; rt < 4; rt++) {
                const int r = wy * 64 + rt * 16 + grp;
                af[rt][0] = A[r * TG_ST + kk];
                af[rt][1] = A[(r + 8) * TG_ST + kk];
                af[rt][2] = A[r * TG_ST + kk + 4];
                af[rt][3] = A[(r + 8) * TG_ST + kk + 4];
            }
#pragma unroll
            for (int ct = 0; ct < 4; ct++) {
                const int j = wx * 32 + ct * 8 + grp;
                bf[ct][0] = Bm[j * TG_ST + kk];
                bf[ct][1] = Bm[j * TG_ST + kk + 4];
            }
#pragma unroll
            for (int rt = 0; rt < 4; rt++)
#pragma unroll
                for (int ct = 0; ct < 4; ct++)
                    mma_f16(acc[rt][ct], af[rt], bf[ct]);
        }
    };

    issue(0);
    issue(1);
    issue(2);
    for (int c = 0; c < 16; c++) {
        if (c + 3 < 16) issue(c + 3);
        if (c <= 12)      asm volatile("cp.async.wait_group 3;" ::: "memory");
        else if (c == 13) asm volatile("cp.async.wait_group 2;" ::: "memory");
        else if (c == 14) asm volatile("cp.async.wait_group 1;" ::: "memory");
        else              asm volatile("cp.async.wait_group 0;" ::: "memory");
        __syncthreads();
        compute(c);
        __syncthreads();
    }

#pragma unroll
    for (int rt = 0; rt < 4; rt++) {
        const int n_lo = n0 + wy * 64 + rt * 16 + grp;
#pragma unroll
        for (int ct = 0; ct < 4; ct++) {
            const int m2 = m0 + wx * 32 + ct * 8 + 2 * tig;
            epi(n_lo, n_lo + 8, m2, acc[rt][ct]);
        }
    }
}

// ---------------------------------------------------------------------------
// QKV projections fused: grid.z selects Q/K/V. Outputs fp16 (V transposed).
// ---------------------------------------------------------------------------
__global__ __launch_bounds__(256, 2)
void qkv_kernel(const float* __restrict__ bq, const float* __restrict__ bk,
                const float* __restrict__ bv)
{
    const int z = blockIdx.z;
    const __half* W = g_wh + (size_t)z * WSLICE;
    const float* bias = (z == 0) ? bq : (z == 1) ? bk : bv;
    const float scale = (z == 0) ? 0.125f : 1.0f;
    const int n0 = blockIdx.x * 128;
    const int m0 = blockIdx.y * 128;

    gemm_core(g_xh, W, n0, m0,
        [&](int n_lo, int n_hi, int m2, const float* c) {
            const float2 bv2 = *(const float2*)(bias + m2);
            const float lx = (c[0] + bv2.x) * scale;
            const float ly = (c[1] + bv2.y) * scale;
            const float hx = (c[2] + bv2.x) * scale;
            const float hy = (c[3] + bv2.y) * scale;
            const int h = m2 >> 6, hd = m2 & 63;
            const int blo = n_lo >> 10, slo = n_lo & 1023;
            const int bhi = n_hi >> 10, shi = n_hi & 1023;
            if (z < 2) {
                __half* out = (z == 0) ? g_qh : g_kh;
                const size_t olo = ((size_t)((blo * H_ + h) * S_ + slo)) * HD_ + hd;
                const size_t ohi = ((size_t)((bhi * H_ + h) * S_ + shi)) * HD_ + hd;
                *(uint32_t*)(out + olo) = f2h2(lx, ly);
                *(uint32_t*)(out + ohi) = f2h2(hx, hy);
            } else {
                const size_t base_lo = ((size_t)(blo * H_ + h)) * HD_ * S_;
                const size_t base_hi = ((size_t)(bhi * H_ + h)) * HD_ * S_;
                g_vt[base_lo + (size_t)hd * S_ + slo] = __float2half_rn(lx);
                g_vt[base_lo + (size_t)(hd + 1) * S_ + slo] = __float2half_rn(ly);
                g_vt[base_hi + (size_t)hd * S_ + shi] = __float2half_rn(hx);
                g_vt[base_hi + (size_t)(hd + 1) * S_ + shi] = __float2half_rn(hy);
            }
        });
}

// ---------------------------------------------------------------------------
// MODE 0 = Wo (g_atth -> g_o2 fp32 + g_o2h fp16); MODE 2 = FFN+resid -> g_att
// ---------------------------------------------------------------------------
template <int MODE>
__global__ __launch_bounds__(256, 2)
void tgemm_kernel(const float* __restrict__ bias)
{
    const __half* X = (MODE == 0) ? g_atth : g_o2h;
    const __half* W = g_wh + (size_t)((MODE == 0) ? 3 : 4) * WSLICE;
    const int n0 = blockIdx.x * 128;
    const int m0 = blockIdx.y * 128;

    gemm_core(X, W, n0, m0,
        [&](int n_lo, int n_hi, int m2, const float* c) {
            const float2 bv2 = *(const float2*)(bias + m2);
            float2 lo = {c[0] + bv2.x, c[1] + bv2.y};
            float2 hi = {c[2] + bv2.x, c[3] + bv2.y};
            const size_t off_lo = (size_t)n_lo * D_ + m2;
            const size_t off_hi = (size_t)n_hi * D_ + m2;
            if (MODE == 0) {
                *(float2*)(g_o2 + off_lo) = lo;
                *(float2*)(g_o2 + off_hi) = hi;
                *(uint32_t*)(g_o2h + off_lo) = f2h2(lo.x, lo.y);
                *(uint32_t*)(g_o2h + off_hi) = f2h2(hi.x, hi.y);
            } else {
                float2 rlo = *(const float2*)(g_o2 + off_lo);
                float2 rhi = *(const float2*)(g_o2 + off_hi);
                lo.x += rlo.x; lo.y += rlo.y;
                hi.x += rhi.x; hi.y += rhi.y;
                *(float2*)(g_att + off_lo) = lo;
                *(float2*)(g_att + off_hi) = hi;
            }
        });
}

// ---------------------------------------------------------------------------
// mem-attention: softmax_k over [ log10(ren+1) + exp(-|ts|) ], causal, per (b,q)
// ---------------------------------------------------------------------------
__global__ __launch_bounds__(256) void mem_kernel(
    const float* __restrict__ ren, const float* __restrict__ ts)
{
    __shared__ float red[8];
    const int bq = blockIdx.x;
    const int q = bq & (S_ - 1);
    const float* rp = ren + (size_t)bq * S_;
    const float* tp = ts + (size_t)bq * S_;
    __half* op = g_memh + (size_t)bq * S_;
    const int tid = threadIdx.x;
    const int k0 = tid * 4;

    float v[4];
    if (k0 <= q) {
        float4 rr = *(const float4*)(rp + k0);
        float4 tt = *(const float4*)(tp + k0);
        float rv[4] = {rr.x, rr.y, rr.z, rr.w};
        float tv[4] = {tt.x, tt.y, tt.z, tt.w};
#pragma unroll
        for (int j = 0; j < 4; j++)
            v[j] = (k0 + j <= q)
                       ? (__log10f(rv[j] + 1.0f) + __expf(-fabsf(tv[j])))
                       : -1e30f;
    } else {
        v[0] = v[1] = v[2] = v[3] = -1e30f;
    }

    float mx = fmaxf(fmaxf(v[0], v[1]), fmaxf(v[2], v[3]));
#pragma unroll
    for (int m = 16; m >= 1; m >>= 1)
        mx = fmaxf(mx, __shfl_xor_sync(0xffffffffu, mx, m));
    if ((tid & 31) == 0) red[tid >> 5] = mx;
    __syncthreads();
    if (tid < 32) {
        float t = (tid < 8) ? red[tid] : -1e30f;
#pragma unroll
        for (int m = 4; m >= 1; m >>= 1)
            t = fmaxf(t, __shfl_xor_sync(0xffffffffu, t, m));
        if (tid == 0) red[0] = t;
    }
    __syncthreads();
    mx = red[0];
    __syncthreads();

    float e[4];
    float s = 0.0f;
#pragma unroll
    for (int j = 0; j < 4; j++) { e[j] = __expf(v[j] - mx); s += e[j]; }
#pragma unroll
    for (int m = 16; m >= 1; m >>= 1)
        s += __shfl_xor_sync(0xffffffffu, s, m);
    if ((tid & 31) == 0) red[tid >> 5] = s;
    __syncthreads();
    if (tid < 32) {
        float t = (tid < 8) ? red[tid] : 0.0f;
#pragma unroll
        for (int m = 4; m >= 1; m >>= 1)
            t += __shfl_xor_sync(0xffffffffu, t, m);
        if (tid == 0) red[0] = t;
    }
    __syncthreads();
    const float inv = 1.0f / red[0];

    uint2 o;
    o.x = f2h2(e[0] * inv, e[1] * inv);
    o.y = f2h2(e[2] * inv, e[3] * inv);
    *(uint2*)(op + k0) = o;
}

// ---------------------------------------------------------------------------
// Flash attention + mem blend, mma.sync fp16 m16n8k16. Output fp16 -> g_atth.
// ---------------------------------------------------------------------------
#define AT_ST 36

__global__ __launch_bounds__(128) void attn_kernel(const float* __restrict__ l1p)
{
    __shared__ uint32_t Ks[64 * AT_ST];
    __shared__ uint32_t Vs[64 * AT_ST];
    __shared__ uint32_t Ms[64 * AT_ST];

    const int bh = blockIdx.x;
    const int qt = (int)gridDim.y - 1 - (int)blockIdx.y;
    const int b = bh >> 3;
    const int tid = threadIdx.x;
    const int wid = tid >> 5;
    const int lane = tid & 31;
    const int grp = lane >> 2;
    const int tig = lane & 3;
    const int r0 = wid * 16 + grp;
    const int r1 = r0 + 8;
    const float l1v = *l1p;

    const uint32_t* Qg = (const uint32_t*)g_qh + ((size_t)bh * S_ + (size_t)qt * 64) * 32;
    const uint4* K4 = (const uint4*)g_kh + (size_t)bh * S_ * 8;
    const uint4* V4 = (const uint4*)g_vt + (size_t)bh * HD_ * 128;
    const uint4* M4 = (const uint4*)g_memh + (size_t)b * S_ * 128;

    uint32_t aQ[4][4];
#pragma unroll
    for (int kk = 0; kk < 4; kk++) {
        aQ[kk][0] = Qg[r0 * 32 + 8 * kk + tig];
        aQ[kk][1] = Qg[r1 * 32 + 8 * kk + tig];
        aQ[kk][2] = Qg[r0 * 32 + 8 * kk + tig + 4];
        aQ[kk][3] = Qg[r1 * 32 + 8 * kk + tig + 4];
    }

    float mi0 = -1e30f, mi1 = -1e30f, ls0 = 0.0f, ls1 = 0.0f;
    float accPV[8][4], accMV[8][4];
#pragma unroll
    for (int nt = 0; nt < 8; nt++)
#pragma unroll
        for (int q = 0; q < 4; q++) { accPV[nt][q] = 0.0f; accMV[nt][q] = 0.0f; }

    for (int kt = 0; kt <= qt; kt++) {
        __syncthreads();
#pragma unroll
        for (int p = 0; p < 4; p++) {
            const int idx = tid + p * 128;
            const int row = idx >> 3;
            const int c = idx & 7;
            uint4 kv = K4[(size_t)(kt * 64 + row) * 8 + c];
            uint4 vv = V4[(size_t)row * 128 + kt * 8 + c];
            uint4 mv = M4[(size_t)(qt * 64 + row) * 128 + kt * 8 + c];
            *(uint4*)(Ks + row * AT_ST + c * 4) = kv;
            *(uint4*)(Vs + row * AT_ST + c * 4) = vv;
            *(uint4*)(Ms + row * AT_ST + c * 4) = mv;
        }
        __syncthreads();

        float sc[8][4];
#pragma unroll
        for (int nt = 0; nt < 8; nt++)
#pragma unroll
            for (int q = 0; q < 4; q++) sc[nt][q] = 0.0f;
#pragma unroll
        for (int kk = 0; kk < 4; kk++) {
#pragma unroll
            for (int nt = 0; nt < 8; nt++) {
                uint32_t bb[2];
                bb[0] = Ks[(8 * nt + grp) * AT_ST + 8 * kk + tig];
                bb[1] = Ks[(8 * nt + grp) * AT_ST + 8 * kk + tig + 4];
                mma_f16(sc[nt], aQ[kk], bb);
            }
        }

        if (kt == qt) {
#pragma unroll
            for (int nt = 0; nt < 8; nt++) {
                const int c0 = 8 * nt + 2 * tig;
                if (c0 > r0) sc[nt][0] = -1e30f;
                if (c0 + 1 > r0) sc[nt][1] = -1e30f;
                if (c0 > r1) sc[nt][2] = -1e30f;
                if (c0 + 1 > r1) sc[nt][3] = -1e30f;
            }
        }

        float mx0 = -1e30f, mx1 = -1e30f;
#pragma unroll
        for (int nt = 0; nt < 8; nt++) {
            mx0 = fmaxf(mx0, fmaxf(sc[nt][0], sc[nt][1]));
            mx1 = fmaxf(mx1, fmaxf(sc[nt][2], sc[nt][3]));
        }
        mx0 = fmaxf(mx0, __shfl_xor_sync(0xffffffffu, mx0, 1));
        mx0 = fmaxf(mx0, __shfl_xor_sync(0xffffffffu, mx0, 2));
        mx1 = fmaxf(mx1, __shfl_xor_sync(0xffffffffu, mx1, 1));
        mx1 = fmaxf(mx1, __shfl_xor_sync(0xffffffffu, mx1, 2));

        const float mn0 = fmaxf(mi0, mx0);
        const float mn1 = fmaxf(mi1, mx1);
        const float p0 = __expf(mi0 - mn0);
        const float p1 = __expf(mi1 - mn1);
        mi0 = mn0; mi1 = mn1;

        float s0 = 0.0f, s1 = 0.0f;
#pragma unroll
        for (int nt = 0; nt < 8; nt++) {
            sc[nt][0] = __expf(sc[nt][0] - mn0); s0 += sc[nt][0];
            sc[nt][1] = __expf(sc[nt][1] - mn0); s0 += sc[nt][1];
            sc[nt][2] = __expf(sc[nt][2] - mn1); s1 += sc[nt][2];
            sc[nt][3] = __expf(sc[nt][3] - mn1); s1 += sc[nt][3];
        }
        s0 += __shfl_xor_sync(0xffffffffu, s0, 1);
        s0 += __shfl_xor_sync(0xffffffffu, s0, 2);
        s1 += __shfl_xor_sync(0xffffffffu, s1, 1);
        s1 += __shfl_xor_sync(0xffffffffu, s1, 2);
        ls0 = ls0 * p0 + s0;
        ls1 = ls1 * p1 + s1;
#pragma unroll
        for (int nt = 0; nt < 8; nt++) {
            accPV[nt][0] *= p0; accPV[nt][1] *= p0;
            accPV[nt][2] *= p1; accPV[nt][3] *= p1;
        }

#pragma unroll
        for (int ks = 0; ks < 4; ks++) {
            uint32_t ap[4], am[4];
            ap[0] = f2h2(sc[2 * ks][0], sc[2 * ks][1]);
            ap[1] = f2h2(sc[2 * ks][2], sc[2 * ks][3]);
            ap[2] = f2h2(sc[2 * ks + 1][0], sc[2 * ks + 1][1]);
            ap[3] = f2h2(sc[2 * ks + 1][2], sc[2 * ks + 1][3]);
            am[0] = Ms[r0 * AT_ST + 8 * ks + tig];
            am[1] = Ms[r1 * AT_ST + 8 * ks + tig];
            am[2] = Ms[r0 * AT_ST + 8 * ks + tig + 4];
            am[3] = Ms[r1 * AT_ST + 8 * ks + tig + 4];
#pragma unroll
            for (int nt = 0; nt < 8; nt++) {
                uint32_t bb[2];
                bb[0] = Vs[(8 * nt + grp) * AT_ST + 8 * ks + tig];
                bb[1] = Vs[(8 * nt + grp) * AT_ST + 8 * ks + tig + 4];
                mma_f16(accPV[nt], ap, bb);
                mma_f16(accMV[nt], am, bb);
            }
        }
    }

    // epilogue: out = (1-l)*accPV/ls + l*accMV, stored fp16
    const float w1 = 1.0f - l1v;
    const float inv0 = w1 / ls0;
    const float inv1 = w1 / ls1;
    const int h = bh & 7;
    __half* Og = g_atth + ((size_t)(b * S_ + qt * 64)) * D_ + h * HD_;
#pragma unroll
    for (int nt = 0; nt < 8; nt++) {
        const int c0 = 8 * nt + 2 * tig;
        *(uint32_t*)(Og + (size_t)r0 * D_ + c0) =
            f2h2(accPV[nt][0] * inv0 + l1v * accMV[nt][0],
                 accPV[nt][1] * inv0 + l1v * accMV[nt][1]);
        *(uint32_t*)(Og + (size_t)r1 * D_ + c0) =
            f2h2(accPV[nt][2] * inv1 + l1v * accMV[nt][2],
                 accPV[nt][3] * inv1 + l1v * accMV[nt][3]);
    }
}

// ---------------------------------------------------------------------------
// LayerNorm over D=512, one block (128 threads) per row. Reads g_att (fp32).
// ---------------------------------------------------------------------------
__global__ __launch_bounds__(128) void ln_kernel(
    const float* __restrict__ g, const float* __restrict__ bb,
    float* __restrict__ out)
{
    __shared__ float r1[4], r2[4];
    const int row = blockIdx.x;
    const int tid = threadIdx.x;
    const float* xr = g_att + (size_t)row * D_;
    float4 v = *(const float4*)(xr + tid * 4);
    float s = v.x + v.y + v.z + v.w;
    float sq = v.x * v.x + v.y * v.y + v.z * v.z + v.w * v.w;
#pragma unroll
    for (int m = 16; m >= 1; m >>= 1) {
        s += __shfl_xor_sync(0xffffffffu, s, m);
        sq += __shfl_xor_sync(0xffffffffu, sq, m);
    }
    if ((tid & 31) == 0) { r1[tid >> 5] = s; r2[tid >> 5] = sq; }
    __syncthreads();
    s = r1[0] + r1[1] + r1[2] + r1[3];
    sq = r2[0] + r2[1] + r2[2] + r2[3];
    const float mu = s * (1.0f / 512.0f);
    const float var = sq * (1.0f / 512.0f) - mu * mu;
    const float rstd = rsqrtf(var + 1e-5f);
    float4 gg = *(const float4*)(g + tid * 4);
    float4 bv = *(const float4*)(bb + tid * 4);
    float4 o;
    o.x = (v.x - mu) * rstd * gg.x + bv.x;
    o.y = (v.y - mu) * rstd * gg.y + bv.y;
    o.z = (v.z - mu) * rstd * gg.z + bv.z;
    o.w = (v.w - mu) * rstd * gg.w + bv.w;
    *(float4*)(out + (size_t)row * D_ + tid * 4) = o;
}

// ---------------------------------------------------------------------------
extern "C" void kernel_launch(void* const* d_in, const int* in_sizes, int n_in,
                              void* d_out, int out_size)
{
    (void)in_sizes; (void)n_in; (void)out_size;
    const float* inputs = (const float*)d_in[1];
    const float* ren    = (const float*)d_in[2];
    const float* tsp    = (const float*)d_in[3];
    const float* Wq = (const float*)d_in[5];
    const float* bq = (const float*)d_in[6];
    const float* Wk = (const float*)d_in[7];
    const float* bk = (const float*)d_in[8];
    const float* Wv = (const float*)d_in[9];
    const float* bv = (const float*)d_in[10];
    const float* Wo = (const float*)d_in[11];
    const float* bo = (const float*)d_in[12];
    const float* W1 = (const float*)d_in[13];
    const float* b1 = (const float*)d_in[14];
    const float* lng = (const float*)d_in[15];
    const float* lnb = (const float*)d_in[16];
    const float* l1  = (const float*)d_in[17];
    float* out = (float*)d_out;

    cudaFuncSetAttribute(qkv_kernel, cudaFuncAttributeMaxDynamicSharedMemorySize, TG_SMEM);
    cudaFuncSetAttribute(tgemm_kernel<0>, cudaFuncAttributeMaxDynamicSharedMemorySize, TG_SMEM);
    cudaFuncSetAttribute(tgemm_kernel<2>, cudaFuncAttributeMaxDynamicSharedMemorySize, TG_SMEM);

    // fp16 pre-conversion: inputs + 5 weight matrices
    cvt_in_kernel<<<NROWS * D_ / 1024, 256>>>(inputs);
    cvt_w_kernel<<<dim3(WSLICE / 1024, 5), 256>>>(Wq, Wk, Wv, Wo, W1);

    const dim3 gq(NROWS / 128, D_ / 128, 3);
    const dim3 gg(NROWS / 128, D_ / 128);

    // QKV projections fused (V transposed; Q pre-scaled 1/8)
    qkv_kernel<<<gq, 256, TG_SMEM>>>(bq, bk, bv);

    // mem-attention probabilities (head-independent, fp16)
    mem_kernel<<<NROWS, 256>>>(ren, tsp);

    // blended flash attention (fp16 tensor) -> g_atth
    attn_kernel<<<dim3(B_ * H_, S_ / 64), 128>>>(l1);

    // Wo projection: g_atth @ Wo^T + bo -> g_o2 (fp32) + g_o2h (fp16)
    tgemm_kernel<0><<<gg, 256, TG_SMEM>>>(bo);
    // FFN + residual: g_o2 + g_o2h @ W1^T + b1 -> g_att
    tgemm_kernel<2><<<gg, 256, TG_SMEM>>>(b1);
    // LayerNorm -> d_out
    ln_kernel<<<NROWS, 128>>>(lng, lnb, out);
}